// round 1
// baseline (speedup 1.0000x reference)
#include <cuda_runtime.h>
#include <cuda_bf16.h>
#include <cstdint>

#define SEQ    4096
#define DIM    512
#define VOCAB  32000
#define NBLK   4
#define HD2    (2*DIM)
#define CHUNK  64
#define NCH    (SEQ/CHUNK)

// ---------------- scratch (device globals; no allocation allowed) ----------
__device__ float g_x [SEQ*DIM];
__device__ float g_xn[SEQ*DIM];
__device__ float g_hg[SEQ*HD2];
__device__ float g_c [SEQ*DIM];
__device__ float g_v [SEQ*DIM];
__device__ float g_P [NCH*DIM];
__device__ float g_S [NCH*DIM];
__device__ float g_H [NCH*DIM];

// ---------------- helpers --------------------------------------------------
__device__ __forceinline__ unsigned f2tf32(float f) {
    unsigned u;
    asm("cvt.rna.tf32.f32 %0, %1;" : "=r"(u) : "f"(f));
    return u;
}

__device__ __forceinline__ void mma_tf32(float* d, const unsigned* a,
                                         const unsigned* b) {
    asm volatile(
        "mma.sync.aligned.m16n8k8.row.col.f32.tf32.tf32.f32 "
        "{%0,%1,%2,%3}, {%4,%5,%6,%7}, {%8,%9}, {%0,%1,%2,%3};"
        : "+f"(d[0]), "+f"(d[1]), "+f"(d[2]), "+f"(d[3])
        : "r"(a[0]), "r"(a[1]), "r"(a[2]), "r"(a[3]),
          "r"(b[0]), "r"(b[1]));
}

// ---------------- kernels --------------------------------------------------

// Embedding gather: x[t, :] = emb[ids[t], :]
__global__ void k_embed(const int* __restrict__ ids,
                        const float* __restrict__ emb) {
    int t = blockIdx.x;
    int d4 = threadIdx.x;                       // 128 threads, float4 each
    int id = ids[t];
    float4 v = ((const float4*)(emb + (size_t)id * DIM))[d4];
    ((float4*)(g_x + (size_t)t * DIM))[d4] = v;
}

// RMSNorm: xn[t,:] = x[t,:] * rsqrt(mean(x^2)+eps) * scale
__global__ void k_rmsnorm(const float* __restrict__ scale) {
    int t = blockIdx.x;
    int tid = threadIdx.x;                      // 128 threads
    float4 v = ((const float4*)(g_x + (size_t)t * DIM))[tid];
    float s = v.x*v.x + v.y*v.y + v.z*v.z + v.w*v.w;
    #pragma unroll
    for (int o = 16; o; o >>= 1) s += __shfl_xor_sync(0xFFFFFFFFu, s, o);
    __shared__ float ws[4];
    if ((tid & 31) == 0) ws[tid >> 5] = s;
    __syncthreads();
    s = ws[0] + ws[1] + ws[2] + ws[3];
    float r = rsqrtf(s * (1.0f / DIM) + 1e-6f);
    float4 sc = ((const float4*)scale)[tid];
    float4 o;
    o.x = v.x * r * sc.x; o.y = v.y * r * sc.y;
    o.z = v.z * r * sc.z; o.w = v.w * r * sc.w;
    ((float4*)(g_xn + (size_t)t * DIM))[tid] = o;
}

// TF32 tensor-core GEMM: C[M,N] = A[M,K] @ B[K,N]. M%128==0, N%128==0, K%16==0.
// BM=BN=128, BK=16, 256 threads = 8 warps, warp tile 64x32.
__global__ void __launch_bounds__(256) k_gemm(const float* __restrict__ A,
                                              const float* __restrict__ B,
                                              float* __restrict__ C,
                                              int M, int N, int K) {
    __shared__ unsigned As[128][20];   // pad 4 -> conflict-free frag loads
    __shared__ unsigned Bs[16][136];   // pad 8 -> conflict-free frag loads

    int tid  = threadIdx.x;
    int lane = tid & 31, warp = tid >> 5;
    int wm = warp & 1;                 // 2 warps along M
    int wn = warp >> 1;                // 4 warps along N
    int g  = lane >> 2, tg = lane & 3;
    int bRow = blockIdx.y * 128, bCol = blockIdx.x * 128;

    float acc[4][4][4];
    #pragma unroll
    for (int mi = 0; mi < 4; mi++)
        #pragma unroll
        for (int ni = 0; ni < 4; ni++)
            #pragma unroll
            for (int r = 0; r < 4; r++) acc[mi][ni][r] = 0.0f;

    for (int kt = 0; kt < K; kt += 16) {
        // ---- load A tile: 128x16 = 512 float4
        #pragma unroll
        for (int i = 0; i < 2; i++) {
            int f  = i * 256 + tid;
            int r  = f >> 2, c4 = f & 3;
            float4 av = *(const float4*)(A + (size_t)(bRow + r) * K + kt + c4 * 4);
            As[r][c4*4+0] = f2tf32(av.x); As[r][c4*4+1] = f2tf32(av.y);
            As[r][c4*4+2] = f2tf32(av.z); As[r][c4*4+3] = f2tf32(av.w);
        }
        // ---- load B tile: 16x128 = 512 float4
        #pragma unroll
        for (int i = 0; i < 2; i++) {
            int f  = i * 256 + tid;
            int r  = f >> 5, c4 = f & 31;
            float4 bv = *(const float4*)(B + (size_t)(kt + r) * N + bCol + c4 * 4);
            Bs[r][c4*4+0] = f2tf32(bv.x); Bs[r][c4*4+1] = f2tf32(bv.y);
            Bs[r][c4*4+2] = f2tf32(bv.z); Bs[r][c4*4+3] = f2tf32(bv.w);
        }
        __syncthreads();

        #pragma unroll
        for (int kk = 0; kk < 2; kk++) {
            int ks = kk * 8;
            unsigned a[4][4], b[4][2];
            #pragma unroll
            for (int mi = 0; mi < 4; mi++) {
                int r0 = wm * 64 + mi * 16 + g;
                a[mi][0] = As[r0    ][ks + tg];
                a[mi][1] = As[r0 + 8][ks + tg];
                a[mi][2] = As[r0    ][ks + tg + 4];
                a[mi][3] = As[r0 + 8][ks + tg + 4];
            }
            #pragma unroll
            for (int ni = 0; ni < 4; ni++) {
                int cb = wn * 32 + ni * 8 + g;
                b[ni][0] = Bs[ks + tg    ][cb];
                b[ni][1] = Bs[ks + tg + 4][cb];
            }
            #pragma unroll
            for (int mi = 0; mi < 4; mi++)
                #pragma unroll
                for (int ni = 0; ni < 4; ni++)
                    mma_tf32(acc[mi][ni], a[mi], b[ni]);
        }
        __syncthreads();
    }

    // ---- epilogue
    #pragma unroll
    for (int mi = 0; mi < 4; mi++) {
        int r0 = bRow + wm * 64 + mi * 16 + g;
        #pragma unroll
        for (int ni = 0; ni < 4; ni++) {
            int c0 = bCol + wn * 32 + ni * 8 + 2 * tg;
            C[(size_t)r0 * N + c0]           = acc[mi][ni][0];
            C[(size_t)r0 * N + c0 + 1]       = acc[mi][ni][1];
            C[(size_t)(r0 + 8) * N + c0]     = acc[mi][ni][2];
            C[(size_t)(r0 + 8) * N + c0 + 1] = acc[mi][ni][3];
        }
    }
}

// Gate elementwise: c = sigmoid(-gate), v = sigmoid(gate) * g(hidden)
__global__ void k_gate() {
    int i  = blockIdx.x * blockDim.x + threadIdx.x;   // over SEQ*DIM/4
    int t  = i >> 7;                                  // DIM/4 = 128
    int d4 = i & 127;
    float4 h4 = ((const float4*)(g_hg + (size_t)t * HD2))[d4];
    float4 q4 = ((const float4*)(g_hg + (size_t)t * HD2 + DIM))[d4];
    float hs[4] = {h4.x, h4.y, h4.z, h4.w};
    float qs[4] = {q4.x, q4.y, q4.z, q4.w};
    float cs[4], vs[4];
    #pragma unroll
    for (int j = 0; j < 4; j++) {
        float z  = 1.0f / (1.0f + expf(-qs[j]));      // sigmoid(gate)
        float c  = 1.0f / (1.0f + expf( qs[j]));      // sigmoid(-gate), exact
        float gg = hs[j] >= 0.0f ? hs[j] + 0.5f
                                 : 1.0f / (1.0f + expf(-hs[j]));
        cs[j] = c; vs[j] = z * gg;
    }
    float4 cv = {cs[0], cs[1], cs[2], cs[3]};
    float4 vv = {vs[0], vs[1], vs[2], vs[3]};
    ((float4*)(g_c + (size_t)t * DIM))[d4] = cv;
    ((float4*)(g_v + (size_t)t * DIM))[d4] = vv;
}

// Scan pass 1: per (chunk, channel) compute P = prod c, S = local scan (h_in=0)
__global__ void k_scan1() {
    int ch = blockIdx.x;
    int d  = blockIdx.y * blockDim.x + threadIdx.x;
    float P = 1.0f, S = 0.0f;
    int base = ch * CHUNK;
    #pragma unroll 8
    for (int j = 0; j < CHUNK; j++) {
        int idx = (base + j) * DIM + d;
        float c = g_c[idx], v = g_v[idx];
        P *= c;
        S = fmaf(c, S, v);
    }
    g_P[ch * DIM + d] = P;
    g_S[ch * DIM + d] = S;
}

// Scan pass 2: sequential combine across NCH chunks (tiny)
__global__ void k_scan2() {
    int d = threadIdx.x;                               // 512 threads, 1 block
    float h = 0.0f;
    for (int k = 0; k < NCH; k++) {
        g_H[k * DIM + d] = h;
        h = fmaf(g_P[k * DIM + d], h, g_S[k * DIM + d]);
    }
}

// Scan pass 3: recompute with carried h, fused residual add into x
__global__ void k_scan3() {
    int ch = blockIdx.x;
    int d  = blockIdx.y * blockDim.x + threadIdx.x;
    float h = g_H[ch * DIM + d];
    int base = ch * CHUNK;
    #pragma unroll 8
    for (int j = 0; j < CHUNK; j++) {
        int idx = (base + j) * DIM + d;
        h = fmaf(g_c[idx], h, g_v[idx]);
        g_x[idx] += h;
    }
}

// ---------------- host -----------------------------------------------------
extern "C" void kernel_launch(void* const* d_in, const int* in_sizes, int n_in,
                              void* d_out, int out_size) {
    const int*   ids    = (const int*)  d_in[0];
    const float* emb    = (const float*)d_in[1];
    const float* w_hg   = (const float*)d_in[2];
    const float* nscale = (const float*)d_in[3];
    const float* fscale = (const float*)d_in[4];
    const float* rw     = (const float*)d_in[5];
    float*       out    = (float*)d_out;

    float *pxn = nullptr, *phg = nullptr;
    cudaGetSymbolAddress((void**)&pxn, g_xn);
    cudaGetSymbolAddress((void**)&phg, g_hg);

    k_embed<<<SEQ, 128>>>(ids, emb);

    for (int i = 0; i < NBLK; i++) {
        k_rmsnorm<<<SEQ, 128>>>(nscale + i * DIM);
        k_gemm<<<dim3(HD2 / 128, SEQ / 128), 256>>>(
            pxn, w_hg + (size_t)i * DIM * HD2, phg, SEQ, HD2, DIM);
        k_gate<<<(SEQ * DIM / 4) / 256, 256>>>();
        k_scan1<<<dim3(NCH, DIM / 128), 128>>>();
        k_scan2<<<1, DIM>>>();
        k_scan3<<<dim3(NCH, DIM / 128), 128>>>();
    }

    k_rmsnorm<<<SEQ, 128>>>(fscale);
    k_gemm<<<dim3(VOCAB / 128, SEQ / 128), 256>>>(
        pxn, rw, out, SEQ, VOCAB, DIM);
}

// round 2
// speedup vs baseline: 1.2498x; 1.2498x over previous
#include <cuda_runtime.h>
#include <cuda_bf16.h>
#include <cstdint>

#define SEQ    4096
#define DIM    512
#define VOCAB  32000
#define NBLK   4
#define HD2    (2*DIM)
#define CHUNK  64
#define NCH    (SEQ/CHUNK)

// GEMM tiling
#define BM 128
#define BN 128
#define BK 32
#define APITCH 36      // 32 + 4 pad (floats)
#define BPITCH 136     // 128 + 8 pad (floats)
#define GEMM_SMEM_BYTES ((2*BM*APITCH + 2*BK*BPITCH) * 4)

// ---------------- scratch (device globals; no allocation allowed) ----------
__device__ float g_x [SEQ*DIM];
__device__ float g_xn[SEQ*DIM];
__device__ float g_hg[SEQ*HD2];
__device__ float g_c [SEQ*DIM];
__device__ float g_v [SEQ*DIM];
__device__ float g_P [NCH*DIM];
__device__ float g_S [NCH*DIM];
__device__ float g_H [NCH*DIM];

// ---------------- helpers --------------------------------------------------
__device__ __forceinline__ unsigned f2tf32(float f) {
    unsigned u;
    asm("cvt.rna.tf32.f32 %0, %1;" : "=r"(u) : "f"(f));
    return u;
}

__device__ __forceinline__ void mma_tf32(float* d, const unsigned* a,
                                         const unsigned* b) {
    asm volatile(
        "mma.sync.aligned.m16n8k8.row.col.f32.tf32.tf32.f32 "
        "{%0,%1,%2,%3}, {%4,%5,%6,%7}, {%8,%9}, {%0,%1,%2,%3};"
        : "+f"(d[0]), "+f"(d[1]), "+f"(d[2]), "+f"(d[3])
        : "r"(a[0]), "r"(a[1]), "r"(a[2]), "r"(a[3]),
          "r"(b[0]), "r"(b[1]));
}

__device__ __forceinline__ void cp16(float* dst, const float* src) {
    unsigned s = (unsigned)__cvta_generic_to_shared(dst);
    asm volatile("cp.async.cg.shared.global [%0], [%1], 16;\n" :: "r"(s), "l"(src));
}

// ---------------- kernels --------------------------------------------------

__global__ void k_embed(const int* __restrict__ ids,
                        const float* __restrict__ emb) {
    int t = blockIdx.x;
    int d4 = threadIdx.x;
    int id = ids[t];
    float4 v = ((const float4*)(emb + (size_t)id * DIM))[d4];
    ((float4*)(g_x + (size_t)t * DIM))[d4] = v;
}

__global__ void k_rmsnorm(const float* __restrict__ scale) {
    int t = blockIdx.x;
    int tid = threadIdx.x;
    float4 v = ((const float4*)(g_x + (size_t)t * DIM))[tid];
    float s = v.x*v.x + v.y*v.y + v.z*v.z + v.w*v.w;
    #pragma unroll
    for (int o = 16; o; o >>= 1) s += __shfl_xor_sync(0xFFFFFFFFu, s, o);
    __shared__ float ws[4];
    if ((tid & 31) == 0) ws[tid >> 5] = s;
    __syncthreads();
    s = ws[0] + ws[1] + ws[2] + ws[3];
    float r = rsqrtf(s * (1.0f / DIM) + 1e-6f);
    float4 sc = ((const float4*)scale)[tid];
    float4 o;
    o.x = v.x * r * sc.x; o.y = v.y * r * sc.y;
    o.z = v.z * r * sc.z; o.w = v.w * r * sc.w;
    ((float4*)(g_xn + (size_t)t * DIM))[tid] = o;
}

// Double-buffered cp.async TF32 GEMM: C[M,N] = A[M,K] @ B[K,N]
// BM=BN=128, BK=32, 256 threads, warp grid 2(M)x4(N), warp tile 64x32.
__global__ void __launch_bounds__(256, 2)
k_gemm(const float* __restrict__ A, const float* __restrict__ B,
       float* __restrict__ C, int M, int N, int K) {
    extern __shared__ float smem[];
    float* As = smem;                   // [2][BM][APITCH]
    float* Bs = smem + 2 * BM * APITCH; // [2][BK][BPITCH]

    int tid  = threadIdx.x;
    int lane = tid & 31, warp = tid >> 5;
    int wm = warp & 1;
    int wn = warp >> 1;
    int g  = lane >> 2, tg = lane & 3;
    int bRow = blockIdx.y * BM, bCol = blockIdx.x * BN;

    const float* Ab = A + (size_t)bRow * K;
    const float* Bb = B + bCol;

    float acc[4][4][4];
    #pragma unroll
    for (int mi = 0; mi < 4; mi++)
        #pragma unroll
        for (int ni = 0; ni < 4; ni++)
            #pragma unroll
            for (int r = 0; r < 4; r++) acc[mi][ni][r] = 0.0f;

    // per-thread load coordinates
    int ar = tid >> 3, ac = (tid & 7) * 4;        // A: 128 rows x 8 f4
    int br = tid >> 5, bc = (tid & 31) * 4;       // B: 32 rows x 32 f4

    int nt = K / BK;

    // prefetch tile 0
    {
        #pragma unroll
        for (int i = 0; i < 4; i++)
            cp16(&As[(ar + i*32) * APITCH + ac], Ab + (size_t)(ar + i*32) * K + ac);
        #pragma unroll
        for (int i = 0; i < 4; i++)
            cp16(&Bs[(br + i*8) * BPITCH + bc], Bb + (size_t)(br + i*8) * N + bc);
        asm volatile("cp.async.commit_group;\n");
    }

    for (int t = 0; t < nt; t++) {
        if (t + 1 < nt) {
            int wb = (t + 1) & 1;
            int k0 = (t + 1) * BK;
            float* Aw = As + wb * BM * APITCH;
            float* Bw = Bs + wb * BK * BPITCH;
            #pragma unroll
            for (int i = 0; i < 4; i++)
                cp16(&Aw[(ar + i*32) * APITCH + ac],
                     Ab + (size_t)(ar + i*32) * K + k0 + ac);
            #pragma unroll
            for (int i = 0; i < 4; i++)
                cp16(&Bw[(br + i*8) * BPITCH + bc],
                     Bb + (size_t)(k0 + br + i*8) * N + bc);
            asm volatile("cp.async.commit_group;\n");
            asm volatile("cp.async.wait_group 1;\n");
        } else {
            asm volatile("cp.async.wait_group 0;\n");
        }
        __syncthreads();

        const float* Ar = As + (t & 1) * BM * APITCH;
        const float* Br = Bs + (t & 1) * BK * BPITCH;

        #pragma unroll
        for (int kk = 0; kk < 4; kk++) {
            int ks = kk * 8;
            unsigned a[4][4], b[4][2];
            #pragma unroll
            for (int mi = 0; mi < 4; mi++) {
                int r0 = wm * 64 + mi * 16 + g;
                a[mi][0] = f2tf32(Ar[ r0      * APITCH + ks + tg    ]);
                a[mi][1] = f2tf32(Ar[(r0 + 8) * APITCH + ks + tg    ]);
                a[mi][2] = f2tf32(Ar[ r0      * APITCH + ks + tg + 4]);
                a[mi][3] = f2tf32(Ar[(r0 + 8) * APITCH + ks + tg + 4]);
            }
            #pragma unroll
            for (int ni = 0; ni < 4; ni++) {
                int cb = wn * 32 + ni * 8 + g;
                b[ni][0] = f2tf32(Br[(ks + tg    ) * BPITCH + cb]);
                b[ni][1] = f2tf32(Br[(ks + tg + 4) * BPITCH + cb]);
            }
            #pragma unroll
            for (int mi = 0; mi < 4; mi++)
                #pragma unroll
                for (int ni = 0; ni < 4; ni++)
                    mma_tf32(acc[mi][ni], a[mi], b[ni]);
        }
        __syncthreads();
    }

    #pragma unroll
    for (int mi = 0; mi < 4; mi++) {
        int r0 = bRow + wm * 64 + mi * 16 + g;
        #pragma unroll
        for (int ni = 0; ni < 4; ni++) {
            int c0 = bCol + wn * 32 + ni * 8 + 2 * tg;
            float2 lo = {acc[mi][ni][0], acc[mi][ni][1]};
            float2 hi = {acc[mi][ni][2], acc[mi][ni][3]};
            *(float2*)(C + (size_t)r0 * N + c0)       = lo;
            *(float2*)(C + (size_t)(r0 + 8) * N + c0) = hi;
        }
    }
}

__global__ void k_gate() {
    int i  = blockIdx.x * blockDim.x + threadIdx.x;
    int t  = i >> 7;
    int d4 = i & 127;
    float4 h4 = ((const float4*)(g_hg + (size_t)t * HD2))[d4];
    float4 q4 = ((const float4*)(g_hg + (size_t)t * HD2 + DIM))[d4];
    float hs[4] = {h4.x, h4.y, h4.z, h4.w};
    float qs[4] = {q4.x, q4.y, q4.z, q4.w};
    float cs[4], vs[4];
    #pragma unroll
    for (int j = 0; j < 4; j++) {
        float z  = 1.0f / (1.0f + expf(-qs[j]));
        float c  = 1.0f / (1.0f + expf( qs[j]));
        float gg = hs[j] >= 0.0f ? hs[j] + 0.5f
                                 : 1.0f / (1.0f + expf(-hs[j]));
        cs[j] = c; vs[j] = z * gg;
    }
    float4 cv = {cs[0], cs[1], cs[2], cs[3]};
    float4 vv = {vs[0], vs[1], vs[2], vs[3]};
    ((float4*)(g_c + (size_t)t * DIM))[d4] = cv;
    ((float4*)(g_v + (size_t)t * DIM))[d4] = vv;
}

__global__ void k_scan1() {
    int ch = blockIdx.x;
    int d  = blockIdx.y * blockDim.x + threadIdx.x;
    float P = 1.0f, S = 0.0f;
    int base = ch * CHUNK;
    #pragma unroll 8
    for (int j = 0; j < CHUNK; j++) {
        int idx = (base + j) * DIM + d;
        float c = g_c[idx], v = g_v[idx];
        P *= c;
        S = fmaf(c, S, v);
    }
    g_P[ch * DIM + d] = P;
    g_S[ch * DIM + d] = S;
}

__global__ void k_scan2() {
    int d = threadIdx.x;
    float h = 0.0f;
    for (int k = 0; k < NCH; k++) {
        g_H[k * DIM + d] = h;
        h = fmaf(g_P[k * DIM + d], h, g_S[k * DIM + d]);
    }
}

__global__ void k_scan3() {
    int ch = blockIdx.x;
    int d  = blockIdx.y * blockDim.x + threadIdx.x;
    float h = g_H[ch * DIM + d];
    int base = ch * CHUNK;
    #pragma unroll 8
    for (int j = 0; j < CHUNK; j++) {
        int idx = (base + j) * DIM + d;
        h = fmaf(g_c[idx], h, g_v[idx]);
        g_x[idx] += h;
    }
}

// ---------------- host -----------------------------------------------------
extern "C" void kernel_launch(void* const* d_in, const int* in_sizes, int n_in,
                              void* d_out, int out_size) {
    const int*   ids    = (const int*)  d_in[0];
    const float* emb    = (const float*)d_in[1];
    const float* w_hg   = (const float*)d_in[2];
    const float* nscale = (const float*)d_in[3];
    const float* fscale = (const float*)d_in[4];
    const float* rw     = (const float*)d_in[5];
    float*       out    = (float*)d_out;

    static bool attr_set = false;
    if (!attr_set) {
        cudaFuncSetAttribute(k_gemm, cudaFuncAttributeMaxDynamicSharedMemorySize,
                             GEMM_SMEM_BYTES);
        attr_set = true;
    }

    float *pxn = nullptr, *phg = nullptr;
    cudaGetSymbolAddress((void**)&pxn, g_xn);
    cudaGetSymbolAddress((void**)&phg, g_hg);

    k_embed<<<SEQ, 128>>>(ids, emb);

    for (int i = 0; i < NBLK; i++) {
        k_rmsnorm<<<SEQ, 128>>>(nscale + i * DIM);
        k_gemm<<<dim3(HD2 / BN, SEQ / BM), 256, GEMM_SMEM_BYTES>>>(
            pxn, w_hg + (size_t)i * DIM * HD2, phg, SEQ, HD2, DIM);
        k_gate<<<(SEQ * DIM / 4) / 256, 256>>>();
        k_scan1<<<dim3(NCH, DIM / 128), 128>>>();
        k_scan2<<<1, DIM>>>();
        k_scan3<<<dim3(NCH, DIM / 128), 128>>>();
    }

    k_rmsnorm<<<SEQ, 128>>>(fscale);
    k_gemm<<<dim3(VOCAB / BN, SEQ / BM), 256, GEMM_SMEM_BYTES>>>(
        pxn, rw, out, SEQ, VOCAB, DIM);
}

// round 4
// speedup vs baseline: 2.0596x; 1.6480x over previous
#include <cuda_runtime.h>
#include <cuda_fp16.h>
#include <cstdint>

#define SEQ    4096
#define DIM    512
#define VOCAB  32000
#define NBLK   4
#define HD2    (2*DIM)
#define CHUNK  64
#define NCH    (SEQ/CHUNK)

// ---- fp16 mma.sync GEMM tiling ----
#define BM 128
#define BN 128
#define BK 64
#define PITCH 72                        // halves per smem row (64 + 8 pad)
#define TILE_BYTES (BM*PITCH*2)         // 18432
#define STAGE_BYTES (2*TILE_BYTES)      // A + B per stage
#define GEMM_SMEM (2*STAGE_BYTES)       // double buffered = 73728

// ---------------- scratch (device globals; no allocation allowed) ----------
__device__ float  g_x [SEQ*DIM];
__device__ __half g_xn[SEQ*DIM];
__device__ float  g_hg[SEQ*HD2];
__device__ float  g_c [SEQ*DIM];
__device__ float  g_v [SEQ*DIM];
__device__ float  g_P [NCH*DIM];
__device__ float  g_S [NCH*DIM];
__device__ float  g_H [NCH*DIM];
__device__ __half g_wt [NBLK*HD2*DIM];          // transposed fp16 w_hg
__device__ __half g_rwt[(size_t)VOCAB*DIM];     // transposed fp16 readout

// ---------------- helpers --------------------------------------------------
__device__ __forceinline__ void cp16(uint32_t saddr, const void* g) {
    asm volatile("cp.async.cg.shared.global [%0], [%1], 16;\n"
                 :: "r"(saddr), "l"(g));
}

__device__ __forceinline__ void ldsm_x4(unsigned* r, uint32_t addr) {
    asm volatile("ldmatrix.sync.aligned.m8n8.x4.shared.b16 {%0,%1,%2,%3}, [%4];"
                 : "=r"(r[0]), "=r"(r[1]), "=r"(r[2]), "=r"(r[3]) : "r"(addr));
}

__device__ __forceinline__ void ldsm_x2(unsigned* r, uint32_t addr) {
    asm volatile("ldmatrix.sync.aligned.m8n8.x2.shared.b16 {%0,%1}, [%2];"
                 : "=r"(r[0]), "=r"(r[1]) : "r"(addr));
}

__device__ __forceinline__ void mma_f16(float* d, const unsigned* a,
                                        const unsigned* b) {
    asm volatile(
        "mma.sync.aligned.m16n8k16.row.col.f32.f16.f16.f32 "
        "{%0,%1,%2,%3}, {%4,%5,%6,%7}, {%8,%9}, {%0,%1,%2,%3};"
        : "+f"(d[0]), "+f"(d[1]), "+f"(d[2]), "+f"(d[3])
        : "r"(a[0]), "r"(a[1]), "r"(a[2]), "r"(a[3]),
          "r"(b[0]), "r"(b[1]));
}

// ---------------- kernels --------------------------------------------------

__global__ void k_embed(const int* __restrict__ ids,
                        const float* __restrict__ emb) {
    int t = blockIdx.x;
    int d4 = threadIdx.x;
    int id = ids[t];
    float4 v = ((const float4*)(emb + (size_t)id * DIM))[d4];
    ((float4*)(g_x + (size_t)t * DIM))[d4] = v;
}

// RMSNorm; writes fp16 (GEMM A operand)
__global__ void k_rmsnorm(const float* __restrict__ scale) {
    int t = blockIdx.x;
    int tid = threadIdx.x;
    float4 v = ((const float4*)(g_x + (size_t)t * DIM))[tid];
    float s = v.x*v.x + v.y*v.y + v.z*v.z + v.w*v.w;
    #pragma unroll
    for (int o = 16; o; o >>= 1) s += __shfl_xor_sync(0xFFFFFFFFu, s, o);
    __shared__ float ws[4];
    if ((tid & 31) == 0) ws[tid >> 5] = s;
    __syncthreads();
    s = ws[0] + ws[1] + ws[2] + ws[3];
    float r = rsqrtf(s * (1.0f / DIM) + 1e-6f);
    float4 sc = ((const float4*)scale)[tid];
    __half2 h0 = __floats2half2_rn(v.x * r * sc.x, v.y * r * sc.y);
    __half2 h1 = __floats2half2_rn(v.z * r * sc.z, v.w * r * sc.w);
    uint2 o = {*(unsigned*)&h0, *(unsigned*)&h1};
    ((uint2*)(g_xn + (size_t)t * DIM))[tid] = o;
}

// Transpose + fp16 round: src [K,N] fp32 row-major -> dst [N,K] fp16 row-major
__global__ void k_transpose(const float* __restrict__ src,
                            __half* __restrict__ dst, int K, int N) {
    __shared__ float t[32][33];
    int n0 = blockIdx.x * 32, k0 = blockIdx.y * 32;
    int x = threadIdx.x;
    #pragma unroll
    for (int r = threadIdx.y; r < 32; r += 8)
        t[r][x] = src[(size_t)(k0 + r) * N + n0 + x];
    __syncthreads();
    #pragma unroll
    for (int r = threadIdx.y; r < 32; r += 8)
        dst[(size_t)(n0 + r) * K + k0 + x] = __float2half_rn(t[x][r]);
}

// fp16 mma.sync GEMM: C[M,N] = A[M,K] @ B[N,K]^T, fp32 accum.
// BM=BN=128, BK=64, double-buffered cp.async, ldmatrix operand loads.
// 256 threads = 8 warps in 2(M) x 4(N); warp tile 64x32.
__global__ void __launch_bounds__(256, 2)
k_gemm_h(const __half* __restrict__ A, const __half* __restrict__ B,
         float* __restrict__ C, int M, int N, int K) {
    extern __shared__ __half smem[];
    uint32_t sbase = (uint32_t)__cvta_generic_to_shared(smem);

    int tid  = threadIdx.x;
    int lane = tid & 31, warp = tid >> 5;
    int wm = warp & 1;
    int wn = warp >> 1;
    int g  = lane >> 2, tg = lane & 3;
    int bRow = blockIdx.y * BM, bCol = blockIdx.x * BN;

    const __half* Ab = A + (size_t)bRow * K;
    const __half* Bb = B + (size_t)bCol * K;

    float acc[4][4][4];
    #pragma unroll
    for (int mi = 0; mi < 4; mi++)
        #pragma unroll
        for (int ni = 0; ni < 4; ni++)
            #pragma unroll
            for (int r = 0; r < 4; r++) acc[mi][ni][r] = 0.0f;

    // loader: 1024 16B-chunks per tile (128 rows x 8), 4 per thread per tile
    auto load_stage = [&](int st, int kt) {
        uint32_t a0 = sbase + st * STAGE_BYTES;
        #pragma unroll
        for (int i = 0; i < 4; i++) {
            int f = tid + i * 256;
            int r = f >> 3, c = f & 7;
            cp16(a0 + (r * PITCH + c * 8) * 2, Ab + (size_t)r * K + kt + c * 8);
        }
        uint32_t b0 = a0 + TILE_BYTES;
        #pragma unroll
        for (int i = 0; i < 4; i++) {
            int f = tid + i * 256;
            int r = f >> 3, c = f & 7;
            cp16(b0 + (r * PITCH + c * 8) * 2, Bb + (size_t)r * K + kt + c * 8);
        }
    };

    int nt = K / BK;

    load_stage(0, 0);
    asm volatile("cp.async.commit_group;" ::: "memory");

    // ldmatrix source rows (per thread)
    int aRow = wm * 64 + (lane & 15);          // + mi*16
    int aColSel = (lane >> 4) * 8;             // 0 or 8
    int bRowT = wn * 32 + (lane & 7);          // + ni*8
    int bColSel = ((lane >> 3) & 1) * 8;       // 0 or 8

    for (int t = 0; t < nt; t++) {
        if (t + 1 < nt) {
            load_stage((t + 1) & 1, (t + 1) * BK);
            asm volatile("cp.async.commit_group;" ::: "memory");
            asm volatile("cp.async.wait_group 1;" ::: "memory");
        } else {
            asm volatile("cp.async.wait_group 0;" ::: "memory");
        }
        __syncthreads();

        uint32_t As = sbase + (t & 1) * STAGE_BYTES;
        uint32_t Bs = As + TILE_BYTES;

        #pragma unroll
        for (int kk = 0; kk < 4; kk++) {
            int ks = kk * 16;
            unsigned a[4][4], b[4][2];
            #pragma unroll
            for (int mi = 0; mi < 4; mi++)
                ldsm_x4(a[mi], As + ((aRow + mi * 16) * PITCH + ks + aColSel) * 2);
            #pragma unroll
            for (int ni = 0; ni < 4; ni++)
                ldsm_x2(b[ni], Bs + ((bRowT + ni * 8) * PITCH + ks + bColSel) * 2);
            #pragma unroll
            for (int mi = 0; mi < 4; mi++)
                #pragma unroll
                for (int ni = 0; ni < 4; ni++)
                    mma_f16(acc[mi][ni], a[mi], b[ni]);
        }
        __syncthreads();
    }

    #pragma unroll
    for (int mi = 0; mi < 4; mi++) {
        int r0 = bRow + wm * 64 + mi * 16 + g;
        #pragma unroll
        for (int ni = 0; ni < 4; ni++) {
            int c0 = bCol + wn * 32 + ni * 8 + 2 * tg;
            float2 lo = {acc[mi][ni][0], acc[mi][ni][1]};
            float2 hi = {acc[mi][ni][2], acc[mi][ni][3]};
            *(float2*)(C + (size_t)r0 * N + c0)       = lo;
            *(float2*)(C + (size_t)(r0 + 8) * N + c0) = hi;
        }
    }
}

__global__ void k_gate() {
    int i  = blockIdx.x * blockDim.x + threadIdx.x;
    int t  = i >> 7;
    int d4 = i & 127;
    float4 h4 = ((const float4*)(g_hg + (size_t)t * HD2))[d4];
    float4 q4 = ((const float4*)(g_hg + (size_t)t * HD2 + DIM))[d4];
    float hs[4] = {h4.x, h4.y, h4.z, h4.w};
    float qs[4] = {q4.x, q4.y, q4.z, q4.w};
    float cs[4], vs[4];
    #pragma unroll
    for (int j = 0; j < 4; j++) {
        float z  = 1.0f / (1.0f + expf(-qs[j]));
        float c  = 1.0f / (1.0f + expf( qs[j]));
        float gg = hs[j] >= 0.0f ? hs[j] + 0.5f
                                 : 1.0f / (1.0f + expf(-hs[j]));
        cs[j] = c; vs[j] = z * gg;
    }
    float4 cv = {cs[0], cs[1], cs[2], cs[3]};
    float4 vv = {vs[0], vs[1], vs[2], vs[3]};
    ((float4*)(g_c + (size_t)t * DIM))[d4] = cv;
    ((float4*)(g_v + (size_t)t * DIM))[d4] = vv;
}

__global__ void k_scan1() {
    int ch = blockIdx.x;
    int d  = blockIdx.y * blockDim.x + threadIdx.x;
    float P = 1.0f, S = 0.0f;
    int base = ch * CHUNK;
    #pragma unroll 8
    for (int j = 0; j < CHUNK; j++) {
        int idx = (base + j) * DIM + d;
        float c = g_c[idx], v = g_v[idx];
        P *= c;
        S = fmaf(c, S, v);
    }
    g_P[ch * DIM + d] = P;
    g_S[ch * DIM + d] = S;
}

__global__ void k_scan2() {
    int d = threadIdx.x;
    float h = 0.0f;
    for (int k = 0; k < NCH; k++) {
        g_H[k * DIM + d] = h;
        h = fmaf(g_P[k * DIM + d], h, g_S[k * DIM + d]);
    }
}

__global__ void k_scan3() {
    int ch = blockIdx.x;
    int d  = blockIdx.y * blockDim.x + threadIdx.x;
    float h = g_H[ch * DIM + d];
    int base = ch * CHUNK;
    #pragma unroll 8
    for (int j = 0; j < CHUNK; j++) {
        int idx = (base + j) * DIM + d;
        h = fmaf(g_c[idx], h, g_v[idx]);
        g_x[idx] += h;
    }
}

// ---------------- host -----------------------------------------------------
extern "C" void kernel_launch(void* const* d_in, const int* in_sizes, int n_in,
                              void* d_out, int out_size) {
    const int*   ids    = (const int*)  d_in[0];
    const float* emb    = (const float*)d_in[1];
    const float* w_hg   = (const float*)d_in[2];
    const float* nscale = (const float*)d_in[3];
    const float* fscale = (const float*)d_in[4];
    const float* rw     = (const float*)d_in[5];
    float*       out    = (float*)d_out;

    static bool attr_set = false;
    if (!attr_set) {
        cudaFuncSetAttribute(k_gemm_h, cudaFuncAttributeMaxDynamicSharedMemorySize,
                             GEMM_SMEM);
        attr_set = true;
    }

    __half *pwt = nullptr, *prwt = nullptr, *pxn = nullptr;
    float  *phg = nullptr;
    cudaGetSymbolAddress((void**)&pxn,  g_xn);
    cudaGetSymbolAddress((void**)&phg,  g_hg);
    cudaGetSymbolAddress((void**)&pwt,  g_wt);
    cudaGetSymbolAddress((void**)&prwt, g_rwt);

    // prepass: transpose + fp16-round weights into [N,K] layout
    for (int i = 0; i < NBLK; i++)
        k_transpose<<<dim3(HD2 / 32, DIM / 32), dim3(32, 8)>>>(
            w_hg + (size_t)i * DIM * HD2, pwt + (size_t)i * HD2 * DIM, DIM, HD2);
    k_transpose<<<dim3(VOCAB / 32, DIM / 32), dim3(32, 8)>>>(rw, prwt, DIM, VOCAB);

    k_embed<<<SEQ, 128>>>(ids, emb);

    for (int i = 0; i < NBLK; i++) {
        k_rmsnorm<<<SEQ, 128>>>(nscale + i * DIM);
        k_gemm_h<<<dim3(HD2 / BN, SEQ / BM), 256, GEMM_SMEM>>>(
            pxn, pwt + (size_t)i * HD2 * DIM, phg, SEQ, HD2, DIM);
        k_gate<<<(SEQ * DIM / 4) / 256, 256>>>();
        k_scan1<<<dim3(NCH, DIM / 128), 128>>>();
        k_scan2<<<1, DIM>>>();
        k_scan3<<<dim3(NCH, DIM / 128), 128>>>();
    }

    k_rmsnorm<<<SEQ, 128>>>(fscale);
    k_gemm_h<<<dim3(VOCAB / BN, SEQ / BM), 256, GEMM_SMEM>>>(
        pxn, prwt, out, SEQ, VOCAB, DIM);
}

// round 5
// speedup vs baseline: 2.0751x; 1.0075x over previous
#include <cuda_runtime.h>
#include <cuda_fp16.h>
#include <cstdint>

#define SEQ    4096
#define DIM    512
#define VOCAB  32000
#define NBLK   4
#define HD2    (2*DIM)
#define CHUNK  64
#define NCH    (SEQ/CHUNK)

// ---- fp16 mma.sync GEMM tiling ----
#define BM 128
#define BN 256
#define BK 64
#define NST 3
#define PITCH 72                        // halves per smem row (64 + 8 pad)
#define A_BYTES (BM*PITCH*2)            // 18432
#define B_BYTES (BN*PITCH*2)            // 36864
#define STAGE_BYTES (A_BYTES + B_BYTES) // 55296
#define GEMM_SMEM (NST*STAGE_BYTES)     // 165888
#define SCAN_SMEM (CHUNK*128*2*4)       // 65536

// ---------------- scratch (device globals; no allocation allowed) ----------
__device__ float  g_x [SEQ*DIM];
__device__ __half g_xn[SEQ*DIM];
__device__ float  g_c [SEQ*DIM];
__device__ float  g_v [SEQ*DIM];
__device__ float  g_P [NCH*DIM];
__device__ float  g_S [NCH*DIM];
__device__ int    g_flag[4*NCH];
__device__ __half g_wt [NBLK*HD2*DIM];          // transposed+interleaved fp16
__device__ __half g_rwt[(size_t)VOCAB*DIM];     // transposed fp16 readout

// ---------------- helpers --------------------------------------------------
__device__ __forceinline__ void cp16(uint32_t saddr, const void* g) {
    asm volatile("cp.async.cg.shared.global [%0], [%1], 16;\n"
                 :: "r"(saddr), "l"(g));
}

__device__ __forceinline__ void ldsm_x4(unsigned* r, uint32_t addr) {
    asm volatile("ldmatrix.sync.aligned.m8n8.x4.shared.b16 {%0,%1,%2,%3}, [%4];"
                 : "=r"(r[0]), "=r"(r[1]), "=r"(r[2]), "=r"(r[3]) : "r"(addr));
}

__device__ __forceinline__ void mma_f16(float* d, const unsigned* a,
                                        const unsigned* b) {
    asm volatile(
        "mma.sync.aligned.m16n8k16.row.col.f32.f16.f16.f32 "
        "{%0,%1,%2,%3}, {%4,%5,%6,%7}, {%8,%9}, {%0,%1,%2,%3};"
        : "+f"(d[0]), "+f"(d[1]), "+f"(d[2]), "+f"(d[3])
        : "r"(a[0]), "r"(a[1]), "r"(a[2]), "r"(a[3]),
          "r"(b[0]), "r"(b[1]));
}

// ---------------- kernels --------------------------------------------------

__global__ void k_embed(const int* __restrict__ ids,
                        const float* __restrict__ emb) {
    int t = blockIdx.x;
    int d4 = threadIdx.x;
    int id = ids[t];
    float4 v = ((const float4*)(emb + (size_t)id * DIM))[d4];
    ((float4*)(g_x + (size_t)t * DIM))[d4] = v;
}

// RMSNorm -> fp16; also re-zeros scan flags (stream-ordered before next scan)
__global__ void k_rmsnorm(const float* __restrict__ scale) {
    int t = blockIdx.x;
    int tid = threadIdx.x;
    if (t < 4 * NCH && tid == 0) g_flag[t] = 0;
    float4 v = ((const float4*)(g_x + (size_t)t * DIM))[tid];
    float s = v.x*v.x + v.y*v.y + v.z*v.z + v.w*v.w;
    #pragma unroll
    for (int o = 16; o; o >>= 1) s += __shfl_xor_sync(0xFFFFFFFFu, s, o);
    __shared__ float ws[4];
    if ((tid & 31) == 0) ws[tid >> 5] = s;
    __syncthreads();
    s = ws[0] + ws[1] + ws[2] + ws[3];
    float r = rsqrtf(s * (1.0f / DIM) + 1e-6f);
    float4 sc = ((const float4*)scale)[tid];
    __half2 h0 = __floats2half2_rn(v.x * r * sc.x, v.y * r * sc.y);
    __half2 h1 = __floats2half2_rn(v.z * r * sc.z, v.w * r * sc.w);
    uint2 o = {*(unsigned*)&h0, *(unsigned*)&h1};
    ((uint2*)(g_xn + (size_t)t * DIM))[tid] = o;
}

// Transpose + fp16: src [K,N] fp32 -> dst [N',K] fp16.
// inter!=0 remaps output row: n<N/2 -> 2n (hidden), else 2(n-N/2)+1 (gate).
__global__ void k_transpose(const float* __restrict__ src,
                            __half* __restrict__ dst, int K, int N, int inter,
                            size_t sstride, size_t dstride) {
    src += blockIdx.z * sstride;
    dst += blockIdx.z * dstride;
    __shared__ float t[32][33];
    int n0 = blockIdx.x * 32, k0 = blockIdx.y * 32;
    int x = threadIdx.x;
    #pragma unroll
    for (int r = threadIdx.y; r < 32; r += 8)
        t[r][x] = src[(size_t)(k0 + r) * N + n0 + x];
    __syncthreads();
    #pragma unroll
    for (int r = threadIdx.y; r < 32; r += 8) {
        int n = n0 + r;
        int nd = inter ? ((n < (N >> 1)) ? 2 * n : 2 * (n - (N >> 1)) + 1) : n;
        dst[(size_t)nd * K + k0 + x] = __float2half_rn(t[x][r]);
    }
}

// fp16 mma.sync GEMM: C[M,N] = A[M,K] @ B[N,K]^T, fp32 accum.
// BM=128, BN=256, BK=64, 3-stage cp.async, 256 thr = 8 warps 2(M)x4(N),
// warp tile 64x64. GATE: fused minGRU gate epilogue (interleaved cols).
template <bool GATE>
__global__ void __launch_bounds__(256, 1)
k_gemm_h(const __half* __restrict__ A, const __half* __restrict__ B,
         float* __restrict__ C, int M, int N, int K) {
    extern __shared__ __half smem[];
    uint32_t sbase = (uint32_t)__cvta_generic_to_shared(smem);

    int tid  = threadIdx.x;
    int lane = tid & 31, warp = tid >> 5;
    int wm = warp & 1;
    int wn = warp >> 1;
    int bRow = blockIdx.y * BM, bCol = blockIdx.x * BN;

    const __half* Ab = A + (size_t)bRow * K;
    const __half* Bb = B + (size_t)bCol * K;

    float acc[4][8][4];
    #pragma unroll
    for (int mi = 0; mi < 4; mi++)
        #pragma unroll
        for (int ni = 0; ni < 8; ni++)
            #pragma unroll
            for (int r = 0; r < 4; r++) acc[mi][ni][r] = 0.0f;

    auto load_stage = [&](int st, int kt) {
        uint32_t a0 = sbase + st * STAGE_BYTES;
        #pragma unroll
        for (int i = 0; i < 4; i++) {
            int f = tid + i * 256;
            int r = f >> 3, c = f & 7;
            cp16(a0 + (r * PITCH + c * 8) * 2, Ab + (size_t)r * K + kt + c * 8);
        }
        uint32_t b0 = a0 + A_BYTES;
        #pragma unroll
        for (int i = 0; i < 8; i++) {
            int f = tid + i * 256;
            int r = f >> 3, c = f & 7;
            cp16(b0 + (r * PITCH + c * 8) * 2, Bb + (size_t)r * K + kt + c * 8);
        }
    };

    int nt = K / BK;     // 8

    #pragma unroll
    for (int s = 0; s < NST - 1; s++) {
        load_stage(s, s * BK);
        asm volatile("cp.async.commit_group;" ::: "memory");
    }

    int aRow = wm * 64 + (lane & 15);
    int aCS  = (lane >> 4) * 8;
    int bMat = lane >> 3;
    int bRowOff = (bMat >> 1) * 8 + (lane & 7);
    int bCS  = (bMat & 1) * 8;

    for (int t = 0; t < nt; t++) {
        if (t + NST - 1 < nt)
            load_stage((t + NST - 1) % NST, (t + NST - 1) * BK);
        asm volatile("cp.async.commit_group;" ::: "memory");
        asm volatile("cp.async.wait_group 2;" ::: "memory");
        __syncthreads();

        uint32_t As = sbase + (t % NST) * STAGE_BYTES;
        uint32_t Bs = As + A_BYTES;

        #pragma unroll
        for (int kk = 0; kk < 4; kk++) {
            int ks = kk * 16;
            unsigned a[4][4], b[4][4];
            #pragma unroll
            for (int mi = 0; mi < 4; mi++)
                ldsm_x4(a[mi], As + ((aRow + mi * 16) * PITCH + ks + aCS) * 2);
            #pragma unroll
            for (int nb = 0; nb < 4; nb++)
                ldsm_x4(b[nb], Bs + ((wn * 64 + nb * 16 + bRowOff) * PITCH
                                     + ks + bCS) * 2);
            #pragma unroll
            for (int mi = 0; mi < 4; mi++)
                #pragma unroll
                for (int ni = 0; ni < 8; ni++)
                    mma_f16(acc[mi][ni], a[mi], &b[ni >> 1][(ni & 1) * 2]);
        }
        __syncthreads();
    }

    int g = lane >> 2, tg = lane & 3;
    if (GATE) {
        // cols (c0, c0+1) = (hidden_d, gate_d), d = c0/2 (interleaved weights)
        #pragma unroll
        for (int mi = 0; mi < 4; mi++) {
            int r0 = bRow + wm * 64 + mi * 16 + g;
            #pragma unroll
            for (int ni = 0; ni < 8; ni++) {
                int d0 = (bCol >> 1) + wn * 32 + ni * 4 + tg;
                #pragma unroll
                for (int h = 0; h < 2; h++) {
                    int r = r0 + 8 * h;
                    float hd = acc[mi][ni][2 * h];
                    float q  = acc[mi][ni][2 * h + 1];
                    float cc = 1.0f / (1.0f + expf(q));
                    float z  = 1.0f / (1.0f + expf(-q));
                    float gg = hd >= 0.0f ? hd + 0.5f
                                          : 1.0f / (1.0f + expf(-hd));
                    g_c[(size_t)r * DIM + d0] = cc;
                    g_v[(size_t)r * DIM + d0] = z * gg;
                }
            }
        }
    } else {
        #pragma unroll
        for (int mi = 0; mi < 4; mi++) {
            int r0 = bRow + wm * 64 + mi * 16 + g;
            #pragma unroll
            for (int ni = 0; ni < 8; ni++) {
                int c0 = bCol + wn * 64 + ni * 8 + 2 * tg;
                float2 lo = {acc[mi][ni][0], acc[mi][ni][1]};
                float2 hi = {acc[mi][ni][2], acc[mi][ni][3]};
                *(float2*)(C + (size_t)r0 * N + c0)       = lo;
                *(float2*)(C + (size_t)(r0 + 8) * N + c0) = hi;
            }
        }
    }
}

// Fused chunked scan (scan1+scan2+scan3): publish (P,S), spin on
// predecessors, back-scan, apply + residual. 256 blocks, all resident.
__global__ void __launch_bounds__(128) k_scan() {
    extern __shared__ float ssm[];
    float* sc = ssm;
    float* sv = ssm + CHUNK * 128;

    int ch  = blockIdx.x;                      // 0..63
    int dg  = blockIdx.y;                      // 0..3
    int tid = threadIdx.x;
    int d   = dg * 128 + tid;

    float P = 1.0f, S = 0.0f;
    #pragma unroll 4
    for (int j = 0; j < CHUNK; j++) {
        int idx = (ch * CHUNK + j) * DIM + d;
        float c = g_c[idx], v = g_v[idx];
        sc[j * 128 + tid] = c;
        sv[j * 128 + tid] = v;
        P *= c;
        S = fmaf(c, S, v);
    }
    g_P[ch * DIM + d] = P;
    g_S[ch * DIM + d] = S;
    __threadfence();
    __syncthreads();
    if (tid == 0)
        *((volatile int*)&g_flag[dg * NCH + ch]) = 1;

    if (tid < ch) {
        volatile int* f = &g_flag[dg * NCH + tid];
        while (*f == 0) __nanosleep(40);
    }
    __syncthreads();
    __threadfence();

    float h = 0.0f;
    for (int j = 0; j < ch; j++)
        h = fmaf(g_P[j * DIM + d], h, g_S[j * DIM + d]);

    #pragma unroll 4
    for (int j = 0; j < CHUNK; j++) {
        h = fmaf(sc[j * 128 + tid], h, sv[j * 128 + tid]);
        int idx = (ch * CHUNK + j) * DIM + d;
        g_x[idx] += h;
    }
}

// ---------------- host -----------------------------------------------------
extern "C" void kernel_launch(void* const* d_in, const int* in_sizes, int n_in,
                              void* d_out, int out_size) {
    const int*   ids    = (const int*)  d_in[0];
    const float* emb    = (const float*)d_in[1];
    const float* w_hg   = (const float*)d_in[2];
    const float* nscale = (const float*)d_in[3];
    const float* fscale = (const float*)d_in[4];
    const float* rw     = (const float*)d_in[5];
    float*       out    = (float*)d_out;

    static bool attr_set = false;
    if (!attr_set) {
        cudaFuncSetAttribute(k_gemm_h<true>,
                             cudaFuncAttributeMaxDynamicSharedMemorySize, GEMM_SMEM);
        cudaFuncSetAttribute(k_gemm_h<false>,
                             cudaFuncAttributeMaxDynamicSharedMemorySize, GEMM_SMEM);
        cudaFuncSetAttribute(k_scan,
                             cudaFuncAttributeMaxDynamicSharedMemorySize, SCAN_SMEM);
        attr_set = true;
    }

    __half *pwt = nullptr, *prwt = nullptr, *pxn = nullptr;
    float  *pc = nullptr;
    cudaGetSymbolAddress((void**)&pxn,  g_xn);
    cudaGetSymbolAddress((void**)&pwt,  g_wt);
    cudaGetSymbolAddress((void**)&prwt, g_rwt);
    cudaGetSymbolAddress((void**)&pc,   g_c);

    // prepass: all 4 block weights in one launch (interleaved), readout plain
    k_transpose<<<dim3(HD2 / 32, DIM / 32, NBLK), dim3(32, 8)>>>(
        w_hg, pwt, DIM, HD2, 1, (size_t)DIM * HD2, (size_t)HD2 * DIM);
    k_transpose<<<dim3(VOCAB / 32, DIM / 32, 1), dim3(32, 8)>>>(
        rw, prwt, DIM, VOCAB, 0, 0, 0);

    k_embed<<<SEQ, 128>>>(ids, emb);

    for (int i = 0; i < NBLK; i++) {
        k_rmsnorm<<<SEQ, 128>>>(nscale + i * DIM);
        k_gemm_h<true><<<dim3(HD2 / BN, SEQ / BM), 256, GEMM_SMEM>>>(
            pxn, pwt + (size_t)i * HD2 * DIM, pc, SEQ, HD2, DIM);
        k_scan<<<dim3(NCH, 4), 128, SCAN_SMEM>>>();
    }

    k_rmsnorm<<<SEQ, 128>>>(fscale);
    k_gemm_h<false><<<dim3(VOCAB / BN, SEQ / BM), 256, GEMM_SMEM>>>(
        pxn, prwt, out, SEQ, VOCAB, DIM);
}

// round 6
// speedup vs baseline: 2.0845x; 1.0045x over previous
#include <cuda_runtime.h>
#include <cuda_fp16.h>
#include <cstdint>

#define SEQ    4096
#define DIM    512
#define VOCAB  32000
#define NBLK   4
#define HD2    (2*DIM)
#define CHUNK  64
#define NCH    (SEQ/CHUNK)

// ---- fp16 mma.sync GEMM tiling ----
#define BM 128
#define BN 256
#define BK 64
#define NST 3
#define PITCH 72                        // halves per smem row (64 + 8 pad)
#define A_BYTES (BM*PITCH*2)            // 18432
#define B_BYTES (BN*PITCH*2)            // 36864
#define STAGE_BYTES (A_BYTES + B_BYTES) // 55296
#define GEMM_SMEM (NST*STAGE_BYTES)     // 165888
#define SCAN_SMEM (CHUNK*128*2*4)       // 65536

// ---------------- scratch (device globals; no allocation allowed) ----------
__device__ float  g_x [SEQ*DIM];
__device__ __half g_xn[SEQ*DIM];
__device__ float  g_c [SEQ*DIM];
__device__ float  g_v [SEQ*DIM];
__device__ float  g_P [NCH*DIM];
__device__ float  g_S [NCH*DIM];
__device__ int    g_flag[4*NCH];
__device__ __half g_wt [NBLK*HD2*DIM];          // transposed+interleaved fp16
__device__ __half g_rwt[(size_t)VOCAB*DIM];     // transposed fp16 readout

// ---------------- helpers --------------------------------------------------
__device__ __forceinline__ void cp16(uint32_t saddr, const void* g) {
    asm volatile("cp.async.cg.shared.global [%0], [%1], 16;\n"
                 :: "r"(saddr), "l"(g));
}

__device__ __forceinline__ void ldsm_x4(unsigned* r, uint32_t addr) {
    asm volatile("ldmatrix.sync.aligned.m8n8.x4.shared.b16 {%0,%1,%2,%3}, [%4];"
                 : "=r"(r[0]), "=r"(r[1]), "=r"(r[2]), "=r"(r[3]) : "r"(addr));
}

__device__ __forceinline__ void mma_f16(float* d, const unsigned* a,
                                        const unsigned* b) {
    asm volatile(
        "mma.sync.aligned.m16n8k16.row.col.f32.f16.f16.f32 "
        "{%0,%1,%2,%3}, {%4,%5,%6,%7}, {%8,%9}, {%0,%1,%2,%3};"
        : "+f"(d[0]), "+f"(d[1]), "+f"(d[2]), "+f"(d[3])
        : "r"(a[0]), "r"(a[1]), "r"(a[2]), "r"(a[3]),
          "r"(b[0]), "r"(b[1]));
}

// ---------------- kernels --------------------------------------------------

__global__ void k_embed(const int* __restrict__ ids,
                        const float* __restrict__ emb) {
    int t = blockIdx.x;
    int d4 = threadIdx.x;
    int id = ids[t];
    float4 v = ((const float4*)(emb + (size_t)id * DIM))[d4];
    ((float4*)(g_x + (size_t)t * DIM))[d4] = v;
}

// RMSNorm -> fp16; also re-zeros scan flags (stream-ordered before next scan)
__global__ void k_rmsnorm(const float* __restrict__ scale) {
    int t = blockIdx.x;
    int tid = threadIdx.x;
    if (t < 4 * NCH && tid == 0) g_flag[t] = 0;
    float4 v = ((const float4*)(g_x + (size_t)t * DIM))[tid];
    float s = v.x*v.x + v.y*v.y + v.z*v.z + v.w*v.w;
    #pragma unroll
    for (int o = 16; o; o >>= 1) s += __shfl_xor_sync(0xFFFFFFFFu, s, o);
    __shared__ float ws[4];
    if ((tid & 31) == 0) ws[tid >> 5] = s;
    __syncthreads();
    s = ws[0] + ws[1] + ws[2] + ws[3];
    float r = rsqrtf(s * (1.0f / DIM) + 1e-6f);
    float4 sc = ((const float4*)scale)[tid];
    __half2 h0 = __floats2half2_rn(v.x * r * sc.x, v.y * r * sc.y);
    __half2 h1 = __floats2half2_rn(v.z * r * sc.z, v.w * r * sc.w);
    uint2 o = {*(unsigned*)&h0, *(unsigned*)&h1};
    ((uint2*)(g_xn + (size_t)t * DIM))[tid] = o;
}

// Transpose + fp16: src [K,N] fp32 -> dst [N',K] fp16.
// inter!=0 remaps output row: n<N/2 -> 2n (hidden), else 2(n-N/2)+1 (gate).
__global__ void k_transpose(const float* __restrict__ src,
                            __half* __restrict__ dst, int K, int N, int inter,
                            size_t sstride, size_t dstride) {
    src += blockIdx.z * sstride;
    dst += blockIdx.z * dstride;
    __shared__ float t[32][33];
    int n0 = blockIdx.x * 32, k0 = blockIdx.y * 32;
    int x = threadIdx.x;
    #pragma unroll
    for (int r = threadIdx.y; r < 32; r += 8)
        t[r][x] = src[(size_t)(k0 + r) * N + n0 + x];
    __syncthreads();
    #pragma unroll
    for (int r = threadIdx.y; r < 32; r += 8) {
        int n = n0 + r;
        int nd = inter ? ((n < (N >> 1)) ? 2 * n : 2 * (n - (N >> 1)) + 1) : n;
        dst[(size_t)nd * K + k0 + x] = __float2half_rn(t[x][r]);
    }
}

// fp16 mma.sync GEMM: C[M,N] = A[M,K] @ B[N,K]^T, fp32 accum.
// BM=128, BN=256, BK=64, 3-stage cp.async, 256 thr = 8 warps 2(M)x4(N),
// warp tile 64x64. GATE: fused minGRU gate epilogue (interleaved cols).
template <bool GATE>
__global__ void __launch_bounds__(256, 1)
k_gemm_h(const __half* __restrict__ A, const __half* __restrict__ B,
         float* __restrict__ C, int M, int N, int K) {
    extern __shared__ __half smem[];
    uint32_t sbase = (uint32_t)__cvta_generic_to_shared(smem);

    int tid  = threadIdx.x;
    int lane = tid & 31, warp = tid >> 5;
    int wm = warp & 1;
    int wn = warp >> 1;
    int bRow = blockIdx.y * BM, bCol = blockIdx.x * BN;

    const __half* Ab = A + (size_t)bRow * K;
    const __half* Bb = B + (size_t)bCol * K;

    float acc[4][8][4];
    #pragma unroll
    for (int mi = 0; mi < 4; mi++)
        #pragma unroll
        for (int ni = 0; ni < 8; ni++)
            #pragma unroll
            for (int r = 0; r < 4; r++) acc[mi][ni][r] = 0.0f;

    auto load_stage = [&](int st, int kt) {
        uint32_t a0 = sbase + st * STAGE_BYTES;
        #pragma unroll
        for (int i = 0; i < 4; i++) {
            int f = tid + i * 256;
            int r = f >> 3, c = f & 7;
            cp16(a0 + (r * PITCH + c * 8) * 2, Ab + (size_t)r * K + kt + c * 8);
        }
        uint32_t b0 = a0 + A_BYTES;
        #pragma unroll
        for (int i = 0; i < 8; i++) {
            int f = tid + i * 256;
            int r = f >> 3, c = f & 7;
            cp16(b0 + (r * PITCH + c * 8) * 2, Bb + (size_t)r * K + kt + c * 8);
        }
    };

    int nt = K / BK;     // 8

    #pragma unroll
    for (int s = 0; s < NST - 1; s++) {
        load_stage(s, s * BK);
        asm volatile("cp.async.commit_group;" ::: "memory");
    }

    int aRow = wm * 64 + (lane & 15);
    int aCS  = (lane >> 4) * 8;
    int bMat = lane >> 3;
    int bRowOff = (bMat >> 1) * 8 + (lane & 7);
    int bCS  = (bMat & 1) * 8;

    for (int t = 0; t < nt; t++) {
        if (t + NST - 1 < nt)
            load_stage((t + NST - 1) % NST, (t + NST - 1) * BK);
        asm volatile("cp.async.commit_group;" ::: "memory");
        asm volatile("cp.async.wait_group 2;" ::: "memory");
        __syncthreads();

        uint32_t As = sbase + (t % NST) * STAGE_BYTES;
        uint32_t Bs = As + A_BYTES;

        #pragma unroll
        for (int kk = 0; kk < 4; kk++) {
            int ks = kk * 16;
            unsigned a[4][4], b[4][4];
            #pragma unroll
            for (int mi = 0; mi < 4; mi++)
                ldsm_x4(a[mi], As + ((aRow + mi * 16) * PITCH + ks + aCS) * 2);
            #pragma unroll
            for (int nb = 0; nb < 4; nb++)
                ldsm_x4(b[nb], Bs + ((wn * 64 + nb * 16 + bRowOff) * PITCH
                                     + ks + bCS) * 2);
            #pragma unroll
            for (int mi = 0; mi < 4; mi++)
                #pragma unroll
                for (int ni = 0; ni < 8; ni++)
                    mma_f16(acc[mi][ni], a[mi], &b[ni >> 1][(ni & 1) * 2]);
        }
        __syncthreads();
    }

    int g = lane >> 2, tg = lane & 3;
    if (GATE) {
        // cols (c0, c0+1) = (hidden_d, gate_d), d = c0/2 (interleaved weights)
        #pragma unroll
        for (int mi = 0; mi < 4; mi++) {
            int r0 = bRow + wm * 64 + mi * 16 + g;
            #pragma unroll
            for (int ni = 0; ni < 8; ni++) {
                int d0 = (bCol >> 1) + wn * 32 + ni * 4 + tg;
                #pragma unroll
                for (int h = 0; h < 2; h++) {
                    int r = r0 + 8 * h;
                    float hd = acc[mi][ni][2 * h];
                    float q  = acc[mi][ni][2 * h + 1];
                    float cc = 1.0f / (1.0f + expf(q));
                    float z  = 1.0f / (1.0f + expf(-q));
                    float gg = hd >= 0.0f ? hd + 0.5f
                                          : 1.0f / (1.0f + expf(-hd));
                    g_c[(size_t)r * DIM + d0] = cc;
                    g_v[(size_t)r * DIM + d0] = z * gg;
                }
            }
        }
    } else {
        #pragma unroll
        for (int mi = 0; mi < 4; mi++) {
            int r0 = bRow + wm * 64 + mi * 16 + g;
            #pragma unroll
            for (int ni = 0; ni < 8; ni++) {
                int c0 = bCol + wn * 64 + ni * 8 + 2 * tg;
                float2 lo = {acc[mi][ni][0], acc[mi][ni][1]};
                float2 hi = {acc[mi][ni][2], acc[mi][ni][3]};
                *(float2*)(C + (size_t)r0 * N + c0)       = lo;
                *(float2*)(C + (size_t)(r0 + 8) * N + c0) = hi;
            }
        }
    }
}

// Fused chunked scan (scan1+scan2+scan3): publish (P,S), spin on
// predecessors, back-scan, apply + residual. 256 blocks, all resident.
__global__ void __launch_bounds__(128) k_scan() {
    extern __shared__ float ssm[];
    float* sc = ssm;
    float* sv = ssm + CHUNK * 128;

    int ch  = blockIdx.x;                      // 0..63
    int dg  = blockIdx.y;                      // 0..3
    int tid = threadIdx.x;
    int d   = dg * 128 + tid;

    float P = 1.0f, S = 0.0f;
    #pragma unroll 4
    for (int j = 0; j < CHUNK; j++) {
        int idx = (ch * CHUNK + j) * DIM + d;
        float c = g_c[idx], v = g_v[idx];
        sc[j * 128 + tid] = c;
        sv[j * 128 + tid] = v;
        P *= c;
        S = fmaf(c, S, v);
    }
    g_P[ch * DIM + d] = P;
    g_S[ch * DIM + d] = S;
    __threadfence();
    __syncthreads();
    if (tid == 0)
        *((volatile int*)&g_flag[dg * NCH + ch]) = 1;

    if (tid < ch) {
        volatile int* f = &g_flag[dg * NCH + tid];
        while (*f == 0) __nanosleep(40);
    }
    __syncthreads();
    __threadfence();

    float h = 0.0f;
    for (int j = 0; j < ch; j++)
        h = fmaf(g_P[j * DIM + d], h, g_S[j * DIM + d]);

    #pragma unroll 4
    for (int j = 0; j < CHUNK; j++) {
        h = fmaf(sc[j * 128 + tid], h, sv[j * 128 + tid]);
        int idx = (ch * CHUNK + j) * DIM + d;
        g_x[idx] += h;
    }
}

// ---------------- host -----------------------------------------------------
extern "C" void kernel_launch(void* const* d_in, const int* in_sizes, int n_in,
                              void* d_out, int out_size) {
    const int*   ids    = (const int*)  d_in[0];
    const float* emb    = (const float*)d_in[1];
    const float* w_hg   = (const float*)d_in[2];
    const float* nscale = (const float*)d_in[3];
    const float* fscale = (const float*)d_in[4];
    const float* rw     = (const float*)d_in[5];
    float*       out    = (float*)d_out;

    static bool attr_set = false;
    if (!attr_set) {
        cudaFuncSetAttribute(k_gemm_h<true>,
                             cudaFuncAttributeMaxDynamicSharedMemorySize, GEMM_SMEM);
        cudaFuncSetAttribute(k_gemm_h<false>,
                             cudaFuncAttributeMaxDynamicSharedMemorySize, GEMM_SMEM);
        cudaFuncSetAttribute(k_scan,
                             cudaFuncAttributeMaxDynamicSharedMemorySize, SCAN_SMEM);
        attr_set = true;
    }

    __half *pwt = nullptr, *prwt = nullptr, *pxn = nullptr;
    float  *pc = nullptr;
    cudaGetSymbolAddress((void**)&pxn,  g_xn);
    cudaGetSymbolAddress((void**)&pwt,  g_wt);
    cudaGetSymbolAddress((void**)&prwt, g_rwt);
    cudaGetSymbolAddress((void**)&pc,   g_c);

    // prepass: all 4 block weights in one launch (interleaved), readout plain
    k_transpose<<<dim3(HD2 / 32, DIM / 32, NBLK), dim3(32, 8)>>>(
        w_hg, pwt, DIM, HD2, 1, (size_t)DIM * HD2, (size_t)HD2 * DIM);
    k_transpose<<<dim3(VOCAB / 32, DIM / 32, 1), dim3(32, 8)>>>(
        rw, prwt, DIM, VOCAB, 0, 0, 0);

    k_embed<<<SEQ, 128>>>(ids, emb);

    for (int i = 0; i < NBLK; i++) {
        k_rmsnorm<<<SEQ, 128>>>(nscale + i * DIM);
        k_gemm_h<true><<<dim3(HD2 / BN, SEQ / BM), 256, GEMM_SMEM>>>(
            pxn, pwt + (size_t)i * HD2 * DIM, pc, SEQ, HD2, DIM);
        k_scan<<<dim3(NCH, 4), 128, SCAN_SMEM>>>();
    }

    k_rmsnorm<<<SEQ, 128>>>(fscale);
    k_gemm_h<false><<<dim3(VOCAB / BN, SEQ / BM), 256, GEMM_SMEM>>>(
        pxn, prwt, out, SEQ, VOCAB, DIM);
}

// round 7
// speedup vs baseline: 2.1733x; 1.0426x over previous
#include <cuda_runtime.h>
#include <cuda_fp16.h>
#include <cstdint>

#define SEQ    4096
#define DIM    512
#define VOCAB  32000
#define NBLK   4
#define HD2    (2*DIM)
#define CHUNK  64
#define NCH    (SEQ/CHUNK)

// ---- fp16 mma.sync GEMM tiling ----
#define BM 128
#define BN 256
#define BK 64
#define NST 3
#define PITCH 72                        // halves per smem row (64 + 8 pad)
#define A_BYTES (BM*PITCH*2)            // 18432
#define B_BYTES (BN*PITCH*2)            // 36864
#define STAGE_BYTES (A_BYTES + B_BYTES) // 55296
#define GEMM_SMEM (NST*STAGE_BYTES)     // 165888
#define SCAN_SMEM (CHUNK*128*2*4)       // 65536

// ---------------- scratch (device globals; no allocation allowed) ----------
__device__ float  g_x [SEQ*DIM];
__device__ __half g_xn[SEQ*DIM];
__device__ float  g_c [SEQ*DIM];
__device__ float  g_v [SEQ*DIM];
__device__ float  g_P [NCH*DIM];
__device__ float  g_S [NCH*DIM];
__device__ int    g_flag[4*NCH];
__device__ __half g_wt [NBLK*HD2*DIM];          // transposed+interleaved fp16
__device__ __half g_rwt[(size_t)VOCAB*DIM];     // transposed fp16 readout

// ---------------- helpers --------------------------------------------------
__device__ __forceinline__ void cp16(uint32_t saddr, const void* g) {
    asm volatile("cp.async.cg.shared.global [%0], [%1], 16;\n"
                 :: "r"(saddr), "l"(g));
}

__device__ __forceinline__ void ldsm_x4(unsigned* r, uint32_t addr) {
    asm volatile("ldmatrix.sync.aligned.m8n8.x4.shared.b16 {%0,%1,%2,%3}, [%4];"
                 : "=r"(r[0]), "=r"(r[1]), "=r"(r[2]), "=r"(r[3]) : "r"(addr));
}

__device__ __forceinline__ void mma_f16(float* d, const unsigned* a,
                                        const unsigned* b) {
    asm volatile(
        "mma.sync.aligned.m16n8k16.row.col.f32.f16.f16.f32 "
        "{%0,%1,%2,%3}, {%4,%5,%6,%7}, {%8,%9}, {%0,%1,%2,%3};"
        : "+f"(d[0]), "+f"(d[1]), "+f"(d[2]), "+f"(d[3])
        : "r"(a[0]), "r"(a[1]), "r"(a[2]), "r"(a[3]),
          "r"(b[0]), "r"(b[1]));
}

// ---------------- kernels --------------------------------------------------

// Warp-per-row RMSNorm -> fp16. GATHER: reads embedding (fused embed) and
// also initializes g_x. Also re-zeros scan flags (stream-ordered).
template <bool GATHER>
__global__ void __launch_bounds__(128) k_rmsnorm(
        const float* __restrict__ scale,
        const int* __restrict__ ids, const float* __restrict__ emb) {
    if (blockIdx.x < 2) g_flag[blockIdx.x * 128 + threadIdx.x] = 0;

    int warp = threadIdx.x >> 5, lane = threadIdx.x & 31;
    int row  = blockIdx.x * 4 + warp;

    const float4* src = GATHER
        ? (const float4*)(emb + (size_t)ids[row] * DIM)
        : (const float4*)(g_x + (size_t)row * DIM);

    float4 v[4];
    float s = 0.0f;
    #pragma unroll
    for (int j = 0; j < 4; j++) {
        v[j] = src[lane + 32 * j];
        s += v[j].x*v[j].x + v[j].y*v[j].y + v[j].z*v[j].z + v[j].w*v[j].w;
    }
    #pragma unroll
    for (int o = 16; o; o >>= 1) s += __shfl_xor_sync(0xFFFFFFFFu, s, o);
    float r = rsqrtf(s * (1.0f / DIM) + 1e-6f);

    float4* dx  = (float4*)(g_x  + (size_t)row * DIM);
    uint2*  dxn = (uint2*)(g_xn + (size_t)row * DIM);
    #pragma unroll
    for (int j = 0; j < 4; j++) {
        if (GATHER) dx[lane + 32 * j] = v[j];
        float4 sc = ((const float4*)scale)[lane + 32 * j];
        __half2 h0 = __floats2half2_rn(v[j].x * r * sc.x, v[j].y * r * sc.y);
        __half2 h1 = __floats2half2_rn(v[j].z * r * sc.z, v[j].w * r * sc.w);
        uint2 o = {*(unsigned*)&h0, *(unsigned*)&h1};
        dxn[lane + 32 * j] = o;
    }
}

// Transpose + fp16: src [K,N] fp32 -> dst [N',K] fp16.
// inter!=0 remaps output row: n<N/2 -> 2n (hidden), else 2(n-N/2)+1 (gate).
__global__ void k_transpose(const float* __restrict__ src,
                            __half* __restrict__ dst, int K, int N, int inter,
                            size_t sstride, size_t dstride) {
    src += blockIdx.z * sstride;
    dst += blockIdx.z * dstride;
    __shared__ float t[32][33];
    int n0 = blockIdx.x * 32, k0 = blockIdx.y * 32;
    int x = threadIdx.x;
    #pragma unroll
    for (int r = threadIdx.y; r < 32; r += 8)
        t[r][x] = src[(size_t)(k0 + r) * N + n0 + x];
    __syncthreads();
    #pragma unroll
    for (int r = threadIdx.y; r < 32; r += 8) {
        int n = n0 + r;
        int nd = inter ? ((n < (N >> 1)) ? 2 * n : 2 * (n - (N >> 1)) + 1) : n;
        dst[(size_t)nd * K + k0 + x] = __float2half_rn(t[x][r]);
    }
}

// fp16 mma.sync GEMM: C[M,N] = A[M,K] @ B[N,K]^T, fp32 accum.
// BM=128, BN=256, BK=64, 3-stage cp.async, single-sync mainloop,
// 256 thr = 8 warps 2(M)x4(N), warp tile 64x64. GATE: fused minGRU epilogue.
template <bool GATE>
__global__ void __launch_bounds__(256, 1)
k_gemm_h(const __half* __restrict__ A, const __half* __restrict__ B,
         float* __restrict__ C, int M, int N, int K) {
    extern __shared__ __half smem[];
    uint32_t sbase = (uint32_t)__cvta_generic_to_shared(smem);

    int tid  = threadIdx.x;
    int lane = tid & 31, warp = tid >> 5;
    int wm = warp & 1;
    int wn = warp >> 1;
    int bRow = blockIdx.y * BM, bCol = blockIdx.x * BN;

    const __half* Ab = A + (size_t)bRow * K;
    const __half* Bb = B + (size_t)bCol * K;

    float acc[4][8][4];
    #pragma unroll
    for (int mi = 0; mi < 4; mi++)
        #pragma unroll
        for (int ni = 0; ni < 8; ni++)
            #pragma unroll
            for (int r = 0; r < 4; r++) acc[mi][ni][r] = 0.0f;

    auto load_stage = [&](int st, int kt) {
        uint32_t a0 = sbase + st * STAGE_BYTES;
        #pragma unroll
        for (int i = 0; i < 4; i++) {
            int f = tid + i * 256;
            int r = f >> 3, c = f & 7;
            cp16(a0 + (r * PITCH + c * 8) * 2, Ab + (size_t)r * K + kt + c * 8);
        }
        uint32_t b0 = a0 + A_BYTES;
        #pragma unroll
        for (int i = 0; i < 8; i++) {
            int f = tid + i * 256;
            int r = f >> 3, c = f & 7;
            cp16(b0 + (r * PITCH + c * 8) * 2, Bb + (size_t)r * K + kt + c * 8);
        }
    };

    int nt = K / BK;     // 8

    #pragma unroll
    for (int s = 0; s < NST - 1; s++) {
        load_stage(s, s * BK);
        asm volatile("cp.async.commit_group;" ::: "memory");
    }

    int aRow = wm * 64 + (lane & 15);
    int aCS  = (lane >> 4) * 8;
    int bMat = lane >> 3;
    int bRowOff = (bMat >> 1) * 8 + (lane & 7);
    int bCS  = (bMat & 1) * 8;

    for (int t = 0; t < nt; t++) {
        if (t < nt - 1)
            asm volatile("cp.async.wait_group 1;" ::: "memory");
        else
            asm volatile("cp.async.wait_group 0;" ::: "memory");
        __syncthreads();

        if (t + NST - 1 < nt) {
            load_stage((t + NST - 1) % NST, (t + NST - 1) * BK);
            asm volatile("cp.async.commit_group;" ::: "memory");
        }

        uint32_t As = sbase + (t % NST) * STAGE_BYTES;
        uint32_t Bs = As + A_BYTES;

        #pragma unroll
        for (int kk = 0; kk < 4; kk++) {
            int ks = kk * 16;
            unsigned a[4][4], b[4][4];
            #pragma unroll
            for (int mi = 0; mi < 4; mi++)
                ldsm_x4(a[mi], As + ((aRow + mi * 16) * PITCH + ks + aCS) * 2);
            #pragma unroll
            for (int nb = 0; nb < 4; nb++)
                ldsm_x4(b[nb], Bs + ((wn * 64 + nb * 16 + bRowOff) * PITCH
                                     + ks + bCS) * 2);
            #pragma unroll
            for (int mi = 0; mi < 4; mi++)
                #pragma unroll
                for (int ni = 0; ni < 8; ni++)
                    mma_f16(acc[mi][ni], a[mi], &b[ni >> 1][(ni & 1) * 2]);
        }
        // no trailing sync: next iteration's barrier covers the
        // write(stage t%NST at iter t+1) vs read(stage t%NST here) hazard
    }

    int g = lane >> 2, tg = lane & 3;
    if (GATE) {
        // cols (c0, c0+1) = (hidden_d, gate_d), d = c0/2 (interleaved weights)
        #pragma unroll
        for (int mi = 0; mi < 4; mi++) {
            int r0 = bRow + wm * 64 + mi * 16 + g;
            #pragma unroll
            for (int ni = 0; ni < 8; ni++) {
                int d0 = (bCol >> 1) + wn * 32 + ni * 4 + tg;
                #pragma unroll
                for (int h = 0; h < 2; h++) {
                    int r = r0 + 8 * h;
                    float hd = acc[mi][ni][2 * h];
                    float q  = acc[mi][ni][2 * h + 1];
                    float eq = __expf(q);
                    float cc = 1.0f / (1.0f + eq);          // sigmoid(-q)
                    float z  = eq * cc;                     // sigmoid(q)
                    float gg = hd >= 0.0f ? hd + 0.5f
                                          : 1.0f / (1.0f + __expf(-hd));
                    g_c[(size_t)r * DIM + d0] = cc;
                    g_v[(size_t)r * DIM + d0] = z * gg;
                }
            }
        }
    } else {
        #pragma unroll
        for (int mi = 0; mi < 4; mi++) {
            int r0 = bRow + wm * 64 + mi * 16 + g;
            #pragma unroll
            for (int ni = 0; ni < 8; ni++) {
                int c0 = bCol + wn * 64 + ni * 8 + 2 * tg;
                float2 lo = {acc[mi][ni][0], acc[mi][ni][1]};
                float2 hi = {acc[mi][ni][2], acc[mi][ni][3]};
                *(float2*)(C + (size_t)r0 * N + c0)       = lo;
                *(float2*)(C + (size_t)(r0 + 8) * N + c0) = hi;
            }
        }
    }
}

// Fused chunked scan: publish (P,S), spin on predecessors, back-scan,
// apply + residual. 256 blocks, all resident.
__global__ void __launch_bounds__(128) k_scan() {
    extern __shared__ float ssm[];
    float* sc = ssm;
    float* sv = ssm + CHUNK * 128;

    int ch  = blockIdx.x;                      // 0..63
    int dg  = blockIdx.y;                      // 0..3
    int tid = threadIdx.x;
    int d   = dg * 128 + tid;

    float P = 1.0f, S = 0.0f;
    #pragma unroll 4
    for (int j = 0; j < CHUNK; j++) {
        int idx = (ch * CHUNK + j) * DIM + d;
        float c = g_c[idx], v = g_v[idx];
        sc[j * 128 + tid] = c;
        sv[j * 128 + tid] = v;
        P *= c;
        S = fmaf(c, S, v);
    }
    g_P[ch * DIM + d] = P;
    g_S[ch * DIM + d] = S;
    __threadfence();
    __syncthreads();
    if (tid == 0)
        *((volatile int*)&g_flag[dg * NCH + ch]) = 1;

    if (tid < ch) {
        volatile int* f = &g_flag[dg * NCH + tid];
        while (*f == 0) __nanosleep(40);
    }
    __syncthreads();
    __threadfence();

    float h = 0.0f;
    for (int j = 0; j < ch; j++)
        h = fmaf(g_P[j * DIM + d], h, g_S[j * DIM + d]);

    #pragma unroll 4
    for (int j = 0; j < CHUNK; j++) {
        h = fmaf(sc[j * 128 + tid], h, sv[j * 128 + tid]);
        int idx = (ch * CHUNK + j) * DIM + d;
        g_x[idx] += h;
    }
}

// ---------------- host -----------------------------------------------------
extern "C" void kernel_launch(void* const* d_in, const int* in_sizes, int n_in,
                              void* d_out, int out_size) {
    const int*   ids    = (const int*)  d_in[0];
    const float* emb    = (const float*)d_in[1];
    const float* w_hg   = (const float*)d_in[2];
    const float* nscale = (const float*)d_in[3];
    const float* fscale = (const float*)d_in[4];
    const float* rw     = (const float*)d_in[5];
    float*       out    = (float*)d_out;

    static bool attr_set = false;
    if (!attr_set) {
        cudaFuncSetAttribute(k_gemm_h<true>,
                             cudaFuncAttributeMaxDynamicSharedMemorySize, GEMM_SMEM);
        cudaFuncSetAttribute(k_gemm_h<false>,
                             cudaFuncAttributeMaxDynamicSharedMemorySize, GEMM_SMEM);
        cudaFuncSetAttribute(k_scan,
                             cudaFuncAttributeMaxDynamicSharedMemorySize, SCAN_SMEM);
        attr_set = true;
    }

    __half *pwt = nullptr, *prwt = nullptr, *pxn = nullptr;
    float  *pc = nullptr;
    cudaGetSymbolAddress((void**)&pxn,  g_xn);
    cudaGetSymbolAddress((void**)&pwt,  g_wt);
    cudaGetSymbolAddress((void**)&prwt, g_rwt);
    cudaGetSymbolAddress((void**)&pc,   g_c);

    // prepass: all 4 block weights in one launch (interleaved), readout plain
    k_transpose<<<dim3(HD2 / 32, DIM / 32, NBLK), dim3(32, 8)>>>(
        w_hg, pwt, DIM, HD2, 1, (size_t)DIM * HD2, (size_t)HD2 * DIM);
    k_transpose<<<dim3(VOCAB / 32, DIM / 32, 1), dim3(32, 8)>>>(
        rw, prwt, DIM, VOCAB, 0, 0, 0);

    for (int i = 0; i < NBLK; i++) {
        if (i == 0)
            k_rmsnorm<true><<<SEQ / 4, 128>>>(nscale, ids, emb);
        else
            k_rmsnorm<false><<<SEQ / 4, 128>>>(nscale + i * DIM, ids, emb);
        k_gemm_h<true><<<dim3(HD2 / BN, SEQ / BM), 256, GEMM_SMEM>>>(
            pxn, pwt + (size_t)i * HD2 * DIM, pc, SEQ, HD2, DIM);
        k_scan<<<dim3(NCH, 4), 128, SCAN_SMEM>>>();
    }

    k_rmsnorm<false><<<SEQ / 4, 128>>>(fscale, ids, emb);
    k_gemm_h<false><<<dim3(VOCAB / BN, SEQ / BM), 256, GEMM_SMEM>>>(
        pxn, prwt, out, SEQ, VOCAB, DIM);
}

// round 8
// speedup vs baseline: 2.2102x; 1.0169x over previous
#include <cuda_runtime.h>
#include <cuda_fp16.h>
#include <cstdint>

#define SEQ    4096
#define DIM    512
#define VOCAB  32000
#define NBLK   4
#define HD2    (2*DIM)
#define CHUNK  64
#define NCH    (SEQ/CHUNK)

// ---- fp16 mma.sync GEMM tiling ----
#define BM 128
#define BK 64
#define NST 3
#define PITCH 72                        // halves per smem row (64 + 8 pad)
#define A_BYTES (BM*PITCH*2)            // 18432
#define SCAN_SMEM (CHUNK*128*2*4)       // 65536
// per-instantiation smem
#define STAGE_B(BNv) ((BNv)*PITCH*2)
#define GSMEM(BNv)   (NST*(A_BYTES + STAGE_B(BNv)))

// ---------------- scratch (device globals; no allocation allowed) ----------
__device__ float  g_x [SEQ*DIM];
__device__ __half g_xn[SEQ*DIM];
__device__ float  g_c [SEQ*DIM];
__device__ float  g_v [SEQ*DIM];
__device__ float  g_P [NCH*DIM];
__device__ float  g_S [NCH*DIM];
__device__ int    g_flag[4*NCH];
__device__ __half g_wt [NBLK*HD2*DIM];          // transposed+interleaved fp16
__device__ __half g_rwt[(size_t)VOCAB*DIM];     // transposed fp16 readout

// ---------------- helpers --------------------------------------------------
__device__ __forceinline__ void cp16(uint32_t saddr, const void* g) {
    asm volatile("cp.async.cg.shared.global [%0], [%1], 16;\n"
                 :: "r"(saddr), "l"(g));
}

__device__ __forceinline__ void ldsm_x4(unsigned* r, uint32_t addr) {
    asm volatile("ldmatrix.sync.aligned.m8n8.x4.shared.b16 {%0,%1,%2,%3}, [%4];"
                 : "=r"(r[0]), "=r"(r[1]), "=r"(r[2]), "=r"(r[3]) : "r"(addr));
}

__device__ __forceinline__ void mma_f16(float* d, const unsigned* a,
                                        const unsigned* b) {
    asm volatile(
        "mma.sync.aligned.m16n8k16.row.col.f32.f16.f16.f32 "
        "{%0,%1,%2,%3}, {%4,%5,%6,%7}, {%8,%9}, {%0,%1,%2,%3};"
        : "+f"(d[0]), "+f"(d[1]), "+f"(d[2]), "+f"(d[3])
        : "r"(a[0]), "r"(a[1]), "r"(a[2]), "r"(a[3]),
          "r"(b[0]), "r"(b[1]));
}

// ---------------- kernels --------------------------------------------------

// Warp-per-row RMSNorm -> fp16. GATHER: fused embedding gather (also fills
// g_x). Also re-zeros scan flags (stream-ordered before the next scan).
template <bool GATHER>
__global__ void __launch_bounds__(128) k_rmsnorm(
        const float* __restrict__ scale,
        const int* __restrict__ ids, const float* __restrict__ emb) {
    if (blockIdx.x < 2) g_flag[blockIdx.x * 128 + threadIdx.x] = 0;

    int warp = threadIdx.x >> 5, lane = threadIdx.x & 31;
    int row  = blockIdx.x * 4 + warp;

    const float4* src = GATHER
        ? (const float4*)(emb + (size_t)ids[row] * DIM)
        : (const float4*)(g_x + (size_t)row * DIM);

    float4 v[4];
    float s = 0.0f;
    #pragma unroll
    for (int j = 0; j < 4; j++) {
        v[j] = src[lane + 32 * j];
        s += v[j].x*v[j].x + v[j].y*v[j].y + v[j].z*v[j].z + v[j].w*v[j].w;
    }
    #pragma unroll
    for (int o = 16; o; o >>= 1) s += __shfl_xor_sync(0xFFFFFFFFu, s, o);
    float r = rsqrtf(s * (1.0f / DIM) + 1e-6f);

    float4* dx  = (float4*)(g_x  + (size_t)row * DIM);
    uint2*  dxn = (uint2*)(g_xn + (size_t)row * DIM);
    #pragma unroll
    for (int j = 0; j < 4; j++) {
        if (GATHER) dx[lane + 32 * j] = v[j];
        float4 sc = ((const float4*)scale)[lane + 32 * j];
        __half2 h0 = __floats2half2_rn(v[j].x * r * sc.x, v[j].y * r * sc.y);
        __half2 h1 = __floats2half2_rn(v[j].z * r * sc.z, v[j].w * r * sc.w);
        uint2 o = {*(unsigned*)&h0, *(unsigned*)&h1};
        dxn[lane + 32 * j] = o;
    }
}

// Transpose + fp16: src [K,N] fp32 -> dst [N',K] fp16.
// inter!=0 remaps output row: n<N/2 -> 2n (hidden), else 2(n-N/2)+1 (gate).
__global__ void k_transpose(const float* __restrict__ src,
                            __half* __restrict__ dst, int K, int N, int inter,
                            size_t sstride, size_t dstride) {
    src += blockIdx.z * sstride;
    dst += blockIdx.z * dstride;
    __shared__ float t[32][33];
    int n0 = blockIdx.x * 32, k0 = blockIdx.y * 32;
    int x = threadIdx.x;
    #pragma unroll
    for (int r = threadIdx.y; r < 32; r += 8)
        t[r][x] = src[(size_t)(k0 + r) * N + n0 + x];
    __syncthreads();
    #pragma unroll
    for (int r = threadIdx.y; r < 32; r += 8) {
        int n = n0 + r;
        int nd = inter ? ((n < (N >> 1)) ? 2 * n : 2 * (n - (N >> 1)) + 1) : n;
        dst[(size_t)nd * K + k0 + x] = __float2half_rn(t[x][r]);
    }
}

// fp16 mma.sync GEMM: C[M,N] = A[M,K] @ B[N,K]^T, fp32 accum.
// BM=128, BN=BNv (template), BK=64, 3-stage cp.async, single-sync mainloop.
// 256 thr = 8 warps 2(M)x4(N), warp tile 64 x BNv/4.
// BNv=128 -> 2 CTAs/SM (occupancy for the latency-bound inner GEMM);
// BNv=256 -> 1 CTA/SM (wave-amortized readout).
template <bool GATE, int BNv>
__global__ void __launch_bounds__(256, BNv == 128 ? 2 : 1)
k_gemm_h(const __half* __restrict__ A, const __half* __restrict__ B,
         float* __restrict__ C, int M, int N, int K) {
    constexpr int STG = A_BYTES + STAGE_B(BNv);
    constexpr int NB  = BNv / 64;      // b ldsm_x4 blocks per warp
    constexpr int NI  = BNv / 32;      // ni (8-col) blocks per warp
    constexpr int WN  = BNv / 4;       // warp N span

    extern __shared__ __half smem[];
    uint32_t sbase = (uint32_t)__cvta_generic_to_shared(smem);

    int tid  = threadIdx.x;
    int lane = tid & 31, warp = tid >> 5;
    int wm = warp & 1;
    int wn = warp >> 1;
    int bRow = blockIdx.y * BM, bCol = blockIdx.x * BNv;

    const __half* Ab = A + (size_t)bRow * K;
    const __half* Bb = B + (size_t)bCol * K;

    float acc[4][NI][4];
    #pragma unroll
    for (int mi = 0; mi < 4; mi++)
        #pragma unroll
        for (int ni = 0; ni < NI; ni++)
            #pragma unroll
            for (int r = 0; r < 4; r++) acc[mi][ni][r] = 0.0f;

    auto load_stage = [&](int st, int kt) {
        uint32_t a0 = sbase + st * STG;
        #pragma unroll
        for (int i = 0; i < 4; i++) {
            int f = tid + i * 256;
            int r = f >> 3, c = f & 7;
            cp16(a0 + (r * PITCH + c * 8) * 2, Ab + (size_t)r * K + kt + c * 8);
        }
        uint32_t b0 = a0 + A_BYTES;
        #pragma unroll
        for (int i = 0; i < BNv / 32; i++) {
            int f = tid + i * 256;
            int r = f >> 3, c = f & 7;
            cp16(b0 + (r * PITCH + c * 8) * 2, Bb + (size_t)r * K + kt + c * 8);
        }
    };

    int nt = K / BK;     // 8

    #pragma unroll
    for (int s = 0; s < NST - 1; s++) {
        load_stage(s, s * BK);
        asm volatile("cp.async.commit_group;" ::: "memory");
    }

    int aRow = wm * 64 + (lane & 15);
    int aCS  = (lane >> 4) * 8;
    int bMat = lane >> 3;
    int bRowOff = (bMat >> 1) * 8 + (lane & 7);
    int bCS  = (bMat & 1) * 8;

    for (int t = 0; t < nt; t++) {
        if (t < nt - 1)
            asm volatile("cp.async.wait_group 1;" ::: "memory");
        else
            asm volatile("cp.async.wait_group 0;" ::: "memory");
        __syncthreads();

        if (t + NST - 1 < nt) {
            load_stage((t + NST - 1) % NST, (t + NST - 1) * BK);
            asm volatile("cp.async.commit_group;" ::: "memory");
        }

        uint32_t As = sbase + (t % NST) * STG;
        uint32_t Bs = As + A_BYTES;

        #pragma unroll
        for (int kk = 0; kk < 4; kk++) {
            int ks = kk * 16;
            unsigned a[4][4], b[NB][4];
            #pragma unroll
            for (int mi = 0; mi < 4; mi++)
                ldsm_x4(a[mi], As + ((aRow + mi * 16) * PITCH + ks + aCS) * 2);
            #pragma unroll
            for (int nb = 0; nb < NB; nb++)
                ldsm_x4(b[nb], Bs + ((wn * WN + nb * 16 + bRowOff) * PITCH
                                     + ks + bCS) * 2);
            #pragma unroll
            for (int mi = 0; mi < 4; mi++)
                #pragma unroll
                for (int ni = 0; ni < NI; ni++)
                    mma_f16(acc[mi][ni], a[mi], &b[ni >> 1][(ni & 1) * 2]);
        }
        // next iteration's barrier covers the stage reuse hazard
    }

    int g = lane >> 2, tg = lane & 3;
    if (GATE) {
        // cols (c0, c0+1) = (hidden_d, gate_d), d = c0/2 (interleaved weights)
        #pragma unroll
        for (int mi = 0; mi < 4; mi++) {
            int r0 = bRow + wm * 64 + mi * 16 + g;
            #pragma unroll
            for (int ni = 0; ni < NI; ni++) {
                int d0 = (bCol >> 1) + wn * (WN / 2) + ni * 4 + tg;
                #pragma unroll
                for (int h = 0; h < 2; h++) {
                    int r = r0 + 8 * h;
                    float hd = acc[mi][ni][2 * h];
                    float q  = acc[mi][ni][2 * h + 1];
                    float eq = __expf(q);
                    float cc = 1.0f / (1.0f + eq);          // sigmoid(-q)
                    float z  = eq * cc;                     // sigmoid(q)
                    float gg = hd >= 0.0f ? hd + 0.5f
                                          : 1.0f / (1.0f + __expf(-hd));
                    g_c[(size_t)r * DIM + d0] = cc;
                    g_v[(size_t)r * DIM + d0] = z * gg;
                }
            }
        }
    } else {
        #pragma unroll
        for (int mi = 0; mi < 4; mi++) {
            int r0 = bRow + wm * 64 + mi * 16 + g;
            #pragma unroll
            for (int ni = 0; ni < NI; ni++) {
                int c0 = bCol + wn * WN + ni * 8 + 2 * tg;
                float2 lo = {acc[mi][ni][0], acc[mi][ni][1]};
                float2 hi = {acc[mi][ni][2], acc[mi][ni][3]};
                *(float2*)(C + (size_t)r0 * N + c0)       = lo;
                *(float2*)(C + (size_t)(r0 + 8) * N + c0) = hi;
            }
        }
    }
}

// Fused chunked scan: publish (P,S), spin on predecessors, back-scan,
// apply + residual. 256 blocks, all resident.
__global__ void __launch_bounds__(128) k_scan() {
    extern __shared__ float ssm[];
    float* sc = ssm;
    float* sv = ssm + CHUNK * 128;

    int ch  = blockIdx.x;                      // 0..63
    int dg  = blockIdx.y;                      // 0..3
    int tid = threadIdx.x;
    int d   = dg * 128 + tid;

    float P = 1.0f, S = 0.0f;
    #pragma unroll 4
    for (int j = 0; j < CHUNK; j++) {
        int idx = (ch * CHUNK + j) * DIM + d;
        float c = g_c[idx], v = g_v[idx];
        sc[j * 128 + tid] = c;
        sv[j * 128 + tid] = v;
        P *= c;
        S = fmaf(c, S, v);
    }
    g_P[ch * DIM + d] = P;
    g_S[ch * DIM + d] = S;
    __threadfence();
    __syncthreads();
    if (tid == 0)
        *((volatile int*)&g_flag[dg * NCH + ch]) = 1;

    if (tid < ch) {
        volatile int* f = &g_flag[dg * NCH + tid];
        while (*f == 0) __nanosleep(40);
    }
    __syncthreads();
    __threadfence();

    float h = 0.0f;
    for (int j = 0; j < ch; j++)
        h = fmaf(g_P[j * DIM + d], h, g_S[j * DIM + d]);

    #pragma unroll 4
    for (int j = 0; j < CHUNK; j++) {
        h = fmaf(sc[j * 128 + tid], h, sv[j * 128 + tid]);
        int idx = (ch * CHUNK + j) * DIM + d;
        g_x[idx] += h;
    }
}

// ---------------- host -----------------------------------------------------
extern "C" void kernel_launch(void* const* d_in, const int* in_sizes, int n_in,
                              void* d_out, int out_size) {
    const int*   ids    = (const int*)  d_in[0];
    const float* emb    = (const float*)d_in[1];
    const float* w_hg   = (const float*)d_in[2];
    const float* nscale = (const float*)d_in[3];
    const float* fscale = (const float*)d_in[4];
    const float* rw     = (const float*)d_in[5];
    float*       out    = (float*)d_out;

    static bool attr_set = false;
    if (!attr_set) {
        cudaFuncSetAttribute(k_gemm_h<true, 128>,
                             cudaFuncAttributeMaxDynamicSharedMemorySize, GSMEM(128));
        cudaFuncSetAttribute(k_gemm_h<false, 256>,
                             cudaFuncAttributeMaxDynamicSharedMemorySize, GSMEM(256));
        cudaFuncSetAttribute(k_scan,
                             cudaFuncAttributeMaxDynamicSharedMemorySize, SCAN_SMEM);
        attr_set = true;
    }

    __half *pwt = nullptr, *prwt = nullptr, *pxn = nullptr;
    float  *pc = nullptr;
    cudaGetSymbolAddress((void**)&pxn,  g_xn);
    cudaGetSymbolAddress((void**)&pwt,  g_wt);
    cudaGetSymbolAddress((void**)&prwt, g_rwt);
    cudaGetSymbolAddress((void**)&pc,   g_c);

    // prepass: all 4 block weights in one launch (interleaved), readout plain
    k_transpose<<<dim3(HD2 / 32, DIM / 32, NBLK), dim3(32, 8)>>>(
        w_hg, pwt, DIM, HD2, 1, (size_t)DIM * HD2, (size_t)HD2 * DIM);
    k_transpose<<<dim3(VOCAB / 32, DIM / 32, 1), dim3(32, 8)>>>(
        rw, prwt, DIM, VOCAB, 0, 0, 0);

    for (int i = 0; i < NBLK; i++) {
        if (i == 0)
            k_rmsnorm<true><<<SEQ / 4, 128>>>(nscale, ids, emb);
        else
            k_rmsnorm<false><<<SEQ / 4, 128>>>(nscale + i * DIM, ids, emb);
        k_gemm_h<true, 128><<<dim3(HD2 / 128, SEQ / BM), 256, GSMEM(128)>>>(
            pxn, pwt + (size_t)i * HD2 * DIM, pc, SEQ, HD2, DIM);
        k_scan<<<dim3(NCH, 4), 128, SCAN_SMEM>>>();
    }

    k_rmsnorm<false><<<SEQ / 4, 128>>>(fscale, ids, emb);
    k_gemm_h<false, 256><<<dim3(VOCAB / 256, SEQ / BM), 256, GSMEM(256)>>>(
        pxn, prwt, out, SEQ, VOCAB, DIM);
}

// round 9
// speedup vs baseline: 2.2183x; 1.0037x over previous
#include <cuda_runtime.h>
#include <cuda_fp16.h>
#include <cstdint>

#define SEQ    4096
#define DIM    512
#define VOCAB  32000
#define NBLK   4
#define HD2    (2*DIM)
#define CHUNK  64
#define NCH    (SEQ/CHUNK)

// ---- readout GEMM tiling (256 thr, 2x4 warps, 64x64 warp tile) ----
#define BM 128
#define BK 64
#define NST 3
#define PITCH 72                        // halves per smem row (64 + 8 pad)
#define A_BYTES (BM*PITCH*2)            // 18432
#define SCAN_SMEM (CHUNK*128*2*4)       // 65536
#define STAGE_B(BNv) ((BNv)*PITCH*2)
#define GSMEM(BNv)   (NST*(A_BYTES + STAGE_B(BNv)))

// ---- inner GEMM tiling (512 thr, 4x4 warps, 32x32 warp tile) ----
#define IBM 128
#define IBN 128
#define ISTG (2*BM*PITCH*2)             // A(128)+B(128) per stage = 36864
#define IGSMEM (NST*ISTG)               // 110592

// ---------------- scratch (device globals; no allocation allowed) ----------
__device__ float  g_x [SEQ*DIM];
__device__ __half g_xn[SEQ*DIM];
__device__ float  g_c [SEQ*DIM];
__device__ float  g_v [SEQ*DIM];
__device__ float  g_P [NCH*DIM];
__device__ float  g_S [NCH*DIM];
__device__ int    g_flag[4*NCH];
__device__ __half g_wt [NBLK*HD2*DIM];          // transposed+interleaved fp16
__device__ __half g_rwt[(size_t)VOCAB*DIM];     // transposed fp16 readout

// ---------------- helpers --------------------------------------------------
__device__ __forceinline__ void cp16(uint32_t saddr, const void* g) {
    asm volatile("cp.async.cg.shared.global [%0], [%1], 16;\n"
                 :: "r"(saddr), "l"(g));
}

__device__ __forceinline__ void ldsm_x4(unsigned* r, uint32_t addr) {
    asm volatile("ldmatrix.sync.aligned.m8n8.x4.shared.b16 {%0,%1,%2,%3}, [%4];"
                 : "=r"(r[0]), "=r"(r[1]), "=r"(r[2]), "=r"(r[3]) : "r"(addr));
}

__device__ __forceinline__ void mma_f16(float* d, const unsigned* a,
                                        const unsigned* b) {
    asm volatile(
        "mma.sync.aligned.m16n8k16.row.col.f32.f16.f16.f32 "
        "{%0,%1,%2,%3}, {%4,%5,%6,%7}, {%8,%9}, {%0,%1,%2,%3};"
        : "+f"(d[0]), "+f"(d[1]), "+f"(d[2]), "+f"(d[3])
        : "r"(a[0]), "r"(a[1]), "r"(a[2]), "r"(a[3]),
          "r"(b[0]), "r"(b[1]));
}

// ---------------- kernels --------------------------------------------------

// Warp-per-row RMSNorm -> fp16. GATHER: fused embedding gather (also fills
// g_x). Also re-zeros scan flags (stream-ordered before the next scan).
template <bool GATHER>
__global__ void __launch_bounds__(128) k_rmsnorm(
        const float* __restrict__ scale,
        const int* __restrict__ ids, const float* __restrict__ emb) {
    if (blockIdx.x < 2) g_flag[blockIdx.x * 128 + threadIdx.x] = 0;

    int warp = threadIdx.x >> 5, lane = threadIdx.x & 31;
    int row  = blockIdx.x * 4 + warp;

    const float4* src = GATHER
        ? (const float4*)(emb + (size_t)ids[row] * DIM)
        : (const float4*)(g_x + (size_t)row * DIM);

    float4 v[4];
    float s = 0.0f;
    #pragma unroll
    for (int j = 0; j < 4; j++) {
        v[j] = src[lane + 32 * j];
        s += v[j].x*v[j].x + v[j].y*v[j].y + v[j].z*v[j].z + v[j].w*v[j].w;
    }
    #pragma unroll
    for (int o = 16; o; o >>= 1) s += __shfl_xor_sync(0xFFFFFFFFu, s, o);
    float r = rsqrtf(s * (1.0f / DIM) + 1e-6f);

    float4* dx  = (float4*)(g_x  + (size_t)row * DIM);
    uint2*  dxn = (uint2*)(g_xn + (size_t)row * DIM);
    #pragma unroll
    for (int j = 0; j < 4; j++) {
        if (GATHER) dx[lane + 32 * j] = v[j];
        float4 sc = ((const float4*)scale)[lane + 32 * j];
        __half2 h0 = __floats2half2_rn(v[j].x * r * sc.x, v[j].y * r * sc.y);
        __half2 h1 = __floats2half2_rn(v[j].z * r * sc.z, v[j].w * r * sc.w);
        uint2 o = {*(unsigned*)&h0, *(unsigned*)&h1};
        dxn[lane + 32 * j] = o;
    }
}

// Transpose + fp16: src [K,N] fp32 -> dst [N',K] fp16.
// inter!=0 remaps output row: n<N/2 -> 2n (hidden), else 2(n-N/2)+1 (gate).
__global__ void k_transpose(const float* __restrict__ src,
                            __half* __restrict__ dst, int K, int N, int inter,
                            size_t sstride, size_t dstride) {
    src += blockIdx.z * sstride;
    dst += blockIdx.z * dstride;
    __shared__ float t[32][33];
    int n0 = blockIdx.x * 32, k0 = blockIdx.y * 32;
    int x = threadIdx.x;
    #pragma unroll
    for (int r = threadIdx.y; r < 32; r += 8)
        t[r][x] = src[(size_t)(k0 + r) * N + n0 + x];
    __syncthreads();
    #pragma unroll
    for (int r = threadIdx.y; r < 32; r += 8) {
        int n = n0 + r;
        int nd = inter ? ((n < (N >> 1)) ? 2 * n : 2 * (n - (N >> 1)) + 1) : n;
        dst[(size_t)nd * K + k0 + x] = __float2half_rn(t[x][r]);
    }
}

// Readout GEMM: C[M,N] = A[M,K] @ B[N,K]^T, fp32 accum. BM=128, BN=256,
// BK=64, 3-stage cp.async, single-sync, 256 thr, warp tile 64x64.
__global__ void __launch_bounds__(256, 1)
k_gemm_ro(const __half* __restrict__ A, const __half* __restrict__ B,
          float* __restrict__ C, int M, int N, int K) {
    constexpr int BNv = 256;
    constexpr int STG = A_BYTES + STAGE_B(BNv);

    extern __shared__ __half smem[];
    uint32_t sbase = (uint32_t)__cvta_generic_to_shared(smem);

    int tid  = threadIdx.x;
    int lane = tid & 31, warp = tid >> 5;
    int wm = warp & 1;
    int wn = warp >> 1;
    int bRow = blockIdx.y * BM, bCol = blockIdx.x * BNv;

    const __half* Ab = A + (size_t)bRow * K;
    const __half* Bb = B + (size_t)bCol * K;

    float acc[4][8][4];
    #pragma unroll
    for (int mi = 0; mi < 4; mi++)
        #pragma unroll
        for (int ni = 0; ni < 8; ni++)
            #pragma unroll
            for (int r = 0; r < 4; r++) acc[mi][ni][r] = 0.0f;

    auto load_stage = [&](int st, int kt) {
        uint32_t a0 = sbase + st * STG;
        #pragma unroll
        for (int i = 0; i < 4; i++) {
            int f = tid + i * 256;
            int r = f >> 3, c = f & 7;
            cp16(a0 + (r * PITCH + c * 8) * 2, Ab + (size_t)r * K + kt + c * 8);
        }
        uint32_t b0 = a0 + A_BYTES;
        #pragma unroll
        for (int i = 0; i < 8; i++) {
            int f = tid + i * 256;
            int r = f >> 3, c = f & 7;
            cp16(b0 + (r * PITCH + c * 8) * 2, Bb + (size_t)r * K + kt + c * 8);
        }
    };

    int nt = K / BK;

    #pragma unroll
    for (int s = 0; s < NST - 1; s++) {
        load_stage(s, s * BK);
        asm volatile("cp.async.commit_group;" ::: "memory");
    }

    int aRow = wm * 64 + (lane & 15);
    int aCS  = (lane >> 4) * 8;
    int bMat = lane >> 3;
    int bRowOff = (bMat >> 1) * 8 + (lane & 7);
    int bCS  = (bMat & 1) * 8;

    for (int t = 0; t < nt; t++) {
        if (t < nt - 1)
            asm volatile("cp.async.wait_group 1;" ::: "memory");
        else
            asm volatile("cp.async.wait_group 0;" ::: "memory");
        __syncthreads();

        if (t + NST - 1 < nt) {
            load_stage((t + NST - 1) % NST, (t + NST - 1) * BK);
            asm volatile("cp.async.commit_group;" ::: "memory");
        }

        uint32_t As = sbase + (t % NST) * STG;
        uint32_t Bs = As + A_BYTES;

        #pragma unroll
        for (int kk = 0; kk < 4; kk++) {
            int ks = kk * 16;
            unsigned a[4][4], b[4][4];
            #pragma unroll
            for (int mi = 0; mi < 4; mi++)
                ldsm_x4(a[mi], As + ((aRow + mi * 16) * PITCH + ks + aCS) * 2);
            #pragma unroll
            for (int nb = 0; nb < 4; nb++)
                ldsm_x4(b[nb], Bs + ((wn * 64 + nb * 16 + bRowOff) * PITCH
                                     + ks + bCS) * 2);
            #pragma unroll
            for (int mi = 0; mi < 4; mi++)
                #pragma unroll
                for (int ni = 0; ni < 8; ni++)
                    mma_f16(acc[mi][ni], a[mi], &b[ni >> 1][(ni & 1) * 2]);
        }
    }

    int g = lane >> 2, tg = lane & 3;
    #pragma unroll
    for (int mi = 0; mi < 4; mi++) {
        int r0 = bRow + wm * 64 + mi * 16 + g;
        #pragma unroll
        for (int ni = 0; ni < 8; ni++) {
            int c0 = bCol + wn * 64 + ni * 8 + 2 * tg;
            float2 lo = {acc[mi][ni][0], acc[mi][ni][1]};
            float2 hi = {acc[mi][ni][2], acc[mi][ni][3]};
            *(float2*)(C + (size_t)r0 * N + c0)       = lo;
            *(float2*)(C + (size_t)(r0 + 8) * N + c0) = hi;
        }
    }
}

// Inner GEMM + fused minGRU gate: 512 threads, 4(M)x4(N) warps, warp tile
// 32x32, BM=BN=128, BK=64, 3-stage cp.async, 2 CTAs/SM (32 warps/SM).
__global__ void __launch_bounds__(512, 2)
k_gemm_in(const __half* __restrict__ A, const __half* __restrict__ B,
          int K) {
    extern __shared__ __half smem[];
    uint32_t sbase = (uint32_t)__cvta_generic_to_shared(smem);

    int tid  = threadIdx.x;
    int lane = tid & 31, warp = tid >> 5;
    int wm = warp & 3;                 // 4 warps along M
    int wn = warp >> 2;                // 4 warps along N
    int bRow = blockIdx.y * IBM, bCol = blockIdx.x * IBN;

    const __half* Ab = A + (size_t)bRow * K;
    const __half* Bb = B + (size_t)bCol * K;

    float acc[2][4][4];
    #pragma unroll
    for (int mi = 0; mi < 2; mi++)
        #pragma unroll
        for (int ni = 0; ni < 4; ni++)
            #pragma unroll
            for (int r = 0; r < 4; r++) acc[mi][ni][r] = 0.0f;

    auto load_stage = [&](int st, int kt) {
        uint32_t a0 = sbase + st * ISTG;
        #pragma unroll
        for (int i = 0; i < 2; i++) {
            int f = tid + i * 512;
            int r = f >> 3, c = f & 7;
            cp16(a0 + (r * PITCH + c * 8) * 2, Ab + (size_t)r * K + kt + c * 8);
        }
        uint32_t b0 = a0 + A_BYTES;
        #pragma unroll
        for (int i = 0; i < 2; i++) {
            int f = tid + i * 512;
            int r = f >> 3, c = f & 7;
            cp16(b0 + (r * PITCH + c * 8) * 2, Bb + (size_t)r * K + kt + c * 8);
        }
    };

    int nt = K / BK;     // 8

    #pragma unroll
    for (int s = 0; s < NST - 1; s++) {
        load_stage(s, s * BK);
        asm volatile("cp.async.commit_group;" ::: "memory");
    }

    int aRow = wm * 32 + (lane & 15);
    int aCS  = (lane >> 4) * 8;
    int bMat = lane >> 3;
    int bRowOff = (bMat >> 1) * 8 + (lane & 7);
    int bCS  = (bMat & 1) * 8;

    for (int t = 0; t < nt; t++) {
        if (t < nt - 1)
            asm volatile("cp.async.wait_group 1;" ::: "memory");
        else
            asm volatile("cp.async.wait_group 0;" ::: "memory");
        __syncthreads();

        if (t + NST - 1 < nt) {
            load_stage((t + NST - 1) % NST, (t + NST - 1) * BK);
            asm volatile("cp.async.commit_group;" ::: "memory");
        }

        uint32_t As = sbase + (t % NST) * ISTG;
        uint32_t Bs = As + A_BYTES;

        #pragma unroll
        for (int kk = 0; kk < 4; kk++) {
            int ks = kk * 16;
            unsigned a[2][4], b[2][4];
            #pragma unroll
            for (int mi = 0; mi < 2; mi++)
                ldsm_x4(a[mi], As + ((aRow + mi * 16) * PITCH + ks + aCS) * 2);
            #pragma unroll
            for (int nb = 0; nb < 2; nb++)
                ldsm_x4(b[nb], Bs + ((wn * 32 + nb * 16 + bRowOff) * PITCH
                                     + ks + bCS) * 2);
            #pragma unroll
            for (int mi = 0; mi < 2; mi++)
                #pragma unroll
                for (int ni = 0; ni < 4; ni++)
                    mma_f16(acc[mi][ni], a[mi], &b[ni >> 1][(ni & 1) * 2]);
        }
    }

    int g = lane >> 2, tg = lane & 3;
    // cols (c0, c0+1) = (hidden_d, gate_d), d = c0/2 (interleaved weights)
    #pragma unroll
    for (int mi = 0; mi < 2; mi++) {
        int r0 = bRow + wm * 32 + mi * 16 + g;
        #pragma unroll
        for (int ni = 0; ni < 4; ni++) {
            int d0 = (bCol >> 1) + wn * 16 + ni * 4 + tg;
            #pragma unroll
            for (int h = 0; h < 2; h++) {
                int r = r0 + 8 * h;
                float hd = acc[mi][ni][2 * h];
                float q  = acc[mi][ni][2 * h + 1];
                float eq = __expf(q);
                float cc = 1.0f / (1.0f + eq);          // sigmoid(-q)
                float z  = eq * cc;                     // sigmoid(q)
                float gg = hd >= 0.0f ? hd + 0.5f
                                      : 1.0f / (1.0f + __expf(-hd));
                g_c[(size_t)r * DIM + d0] = cc;
                g_v[(size_t)r * DIM + d0] = z * gg;
            }
        }
    }
}

// Fused chunked scan: publish (P,S), spin on predecessors, back-scan,
// apply + residual. 256 blocks, all resident.
__global__ void __launch_bounds__(128) k_scan() {
    extern __shared__ float ssm[];
    float* sc = ssm;
    float* sv = ssm + CHUNK * 128;

    int ch  = blockIdx.x;                      // 0..63
    int dg  = blockIdx.y;                      // 0..3
    int tid = threadIdx.x;
    int d   = dg * 128 + tid;

    float P = 1.0f, S = 0.0f;
    #pragma unroll 4
    for (int j = 0; j < CHUNK; j++) {
        int idx = (ch * CHUNK + j) * DIM + d;
        float c = g_c[idx], v = g_v[idx];
        sc[j * 128 + tid] = c;
        sv[j * 128 + tid] = v;
        P *= c;
        S = fmaf(c, S, v);
    }
    g_P[ch * DIM + d] = P;
    g_S[ch * DIM + d] = S;
    __threadfence();
    __syncthreads();
    if (tid == 0)
        *((volatile int*)&g_flag[dg * NCH + ch]) = 1;

    if (tid < ch) {
        volatile int* f = &g_flag[dg * NCH + tid];
        while (*f == 0) __nanosleep(40);
    }
    __syncthreads();
    __threadfence();

    float h = 0.0f;
    for (int j = 0; j < ch; j++)
        h = fmaf(g_P[j * DIM + d], h, g_S[j * DIM + d]);

    #pragma unroll 4
    for (int j = 0; j < CHUNK; j++) {
        h = fmaf(sc[j * 128 + tid], h, sv[j * 128 + tid]);
        int idx = (ch * CHUNK + j) * DIM + d;
        g_x[idx] += h;
    }
}

// ---------------- host -----------------------------------------------------
extern "C" void kernel_launch(void* const* d_in, const int* in_sizes, int n_in,
                              void* d_out, int out_size) {
    const int*   ids    = (const int*)  d_in[0];
    const float* emb    = (const float*)d_in[1];
    const float* w_hg   = (const float*)d_in[2];
    const float* nscale = (const float*)d_in[3];
    const float* fscale = (const float*)d_in[4];
    const float* rw     = (const float*)d_in[5];
    float*       out    = (float*)d_out;

    static bool attr_set = false;
    if (!attr_set) {
        cudaFuncSetAttribute(k_gemm_in,
                             cudaFuncAttributeMaxDynamicSharedMemorySize, IGSMEM);
        cudaFuncSetAttribute(k_gemm_ro,
                             cudaFuncAttributeMaxDynamicSharedMemorySize, GSMEM(256));
        cudaFuncSetAttribute(k_scan,
                             cudaFuncAttributeMaxDynamicSharedMemorySize, SCAN_SMEM);
        attr_set = true;
    }

    __half *pwt = nullptr, *prwt = nullptr, *pxn = nullptr;
    cudaGetSymbolAddress((void**)&pxn,  g_xn);
    cudaGetSymbolAddress((void**)&pwt,  g_wt);
    cudaGetSymbolAddress((void**)&prwt, g_rwt);

    // prepass: all 4 block weights in one launch (interleaved), readout plain
    k_transpose<<<dim3(HD2 / 32, DIM / 32, NBLK), dim3(32, 8)>>>(
        w_hg, pwt, DIM, HD2, 1, (size_t)DIM * HD2, (size_t)HD2 * DIM);
    k_transpose<<<dim3(VOCAB / 32, DIM / 32, 1), dim3(32, 8)>>>(
        rw, prwt, DIM, VOCAB, 0, 0, 0);

    for (int i = 0; i < NBLK; i++) {
        if (i == 0)
            k_rmsnorm<true><<<SEQ / 4, 128>>>(nscale, ids, emb);
        else
            k_rmsnorm<false><<<SEQ / 4, 128>>>(nscale + i * DIM, ids, emb);
        k_gemm_in<<<dim3(HD2 / IBN, SEQ / IBM), 512, IGSMEM>>>(
            pxn, pwt + (size_t)i * HD2 * DIM, DIM);
        k_scan<<<dim3(NCH, 4), 128, SCAN_SMEM>>>();
    }

    k_rmsnorm<false><<<SEQ / 4, 128>>>(fscale, ids, emb);
    k_gemm_ro<<<dim3(VOCAB / 256, SEQ / BM), 256, GSMEM(256)>>>(
        pxn, prwt, out, SEQ, VOCAB, DIM);
}

// round 10
// speedup vs baseline: 2.2235x; 1.0024x over previous
#include <cuda_runtime.h>
#include <cuda_fp16.h>
#include <cstdint>

#define SEQ    4096
#define DIM    512
#define VOCAB  32000
#define NBLK   4
#define HD2    (2*DIM)
#define CHUNK  64
#define NCH    (SEQ/CHUNK)

// ---- shared GEMM tiling constants ----
#define BM 128
#define BK 64
#define NST 3
#define PITCH 72                        // halves per smem row (64 + 8 pad)
#define A_BYTES (BM*PITCH*2)            // 18432
#define SCAN_SMEM (CHUNK*128*2*4)       // 65536
#define STAGE_B(BNv) ((BNv)*PITCH*2)
#define GSMEM(BNv)   (NST*(A_BYTES + STAGE_B(BNv)))

// ---------------- scratch (device globals; no allocation allowed) ----------
__device__ float  g_x [SEQ*DIM];
__device__ __half g_xn[SEQ*DIM];
__device__ float  g_c [SEQ*DIM];
__device__ float  g_v [SEQ*DIM];
__device__ float  g_P [NCH*DIM];
__device__ float  g_S [NCH*DIM];
__device__ int    g_flag[4*NCH];
__device__ __half g_wt [NBLK*HD2*DIM];          // transposed+interleaved fp16
__device__ __half g_rwt[(size_t)VOCAB*DIM];     // transposed fp16 readout

// ---------------- helpers --------------------------------------------------
__device__ __forceinline__ void cp16(uint32_t saddr, const void* g) {
    asm volatile("cp.async.cg.shared.global [%0], [%1], 16;\n"
                 :: "r"(saddr), "l"(g));
}

__device__ __forceinline__ void ldsm_x4(unsigned* r, uint32_t addr) {
    asm volatile("ldmatrix.sync.aligned.m8n8.x4.shared.b16 {%0,%1,%2,%3}, [%4];"
                 : "=r"(r[0]), "=r"(r[1]), "=r"(r[2]), "=r"(r[3]) : "r"(addr));
}

__device__ __forceinline__ void mma_f16(float* d, const unsigned* a,
                                        const unsigned* b) {
    asm volatile(
        "mma.sync.aligned.m16n8k16.row.col.f32.f16.f16.f32 "
        "{%0,%1,%2,%3}, {%4,%5,%6,%7}, {%8,%9}, {%0,%1,%2,%3};"
        : "+f"(d[0]), "+f"(d[1]), "+f"(d[2]), "+f"(d[3])
        : "r"(a[0]), "r"(a[1]), "r"(a[2]), "r"(a[3]),
          "r"(b[0]), "r"(b[1]));
}

// ---------------- kernels --------------------------------------------------

// Warp-per-row RMSNorm -> fp16. GATHER: fused embedding gather (also fills
// g_x). Also re-zeros scan flags (stream-ordered before the next scan).
template <bool GATHER>
__global__ void __launch_bounds__(128) k_rmsnorm(
        const float* __restrict__ scale,
        const int* __restrict__ ids, const float* __restrict__ emb) {
    if (blockIdx.x < 2) g_flag[blockIdx.x * 128 + threadIdx.x] = 0;

    int warp = threadIdx.x >> 5, lane = threadIdx.x & 31;
    int row  = blockIdx.x * 4 + warp;

    const float4* src = GATHER
        ? (const float4*)(emb + (size_t)ids[row] * DIM)
        : (const float4*)(g_x + (size_t)row * DIM);

    float4 v[4];
    float s = 0.0f;
    #pragma unroll
    for (int j = 0; j < 4; j++) {
        v[j] = src[lane + 32 * j];
        s += v[j].x*v[j].x + v[j].y*v[j].y + v[j].z*v[j].z + v[j].w*v[j].w;
    }
    #pragma unroll
    for (int o = 16; o; o >>= 1) s += __shfl_xor_sync(0xFFFFFFFFu, s, o);
    float r = rsqrtf(s * (1.0f / DIM) + 1e-6f);

    float4* dx  = (float4*)(g_x  + (size_t)row * DIM);
    uint2*  dxn = (uint2*)(g_xn + (size_t)row * DIM);
    #pragma unroll
    for (int j = 0; j < 4; j++) {
        if (GATHER) dx[lane + 32 * j] = v[j];
        float4 sc = ((const float4*)scale)[lane + 32 * j];
        __half2 h0 = __floats2half2_rn(v[j].x * r * sc.x, v[j].y * r * sc.y);
        __half2 h1 = __floats2half2_rn(v[j].z * r * sc.z, v[j].w * r * sc.w);
        uint2 o = {*(unsigned*)&h0, *(unsigned*)&h1};
        dxn[lane + 32 * j] = o;
    }
}

// Transpose + fp16: src [K,N] fp32 -> dst [N',K] fp16.
// inter!=0 remaps output row: n<N/2 -> 2n (hidden), else 2(n-N/2)+1 (gate).
__global__ void k_transpose(const float* __restrict__ src,
                            __half* __restrict__ dst, int K, int N, int inter,
                            size_t sstride, size_t dstride) {
    src += blockIdx.z * sstride;
    dst += blockIdx.z * dstride;
    __shared__ float t[32][33];
    int n0 = blockIdx.x * 32, k0 = blockIdx.y * 32;
    int x = threadIdx.x;
    #pragma unroll
    for (int r = threadIdx.y; r < 32; r += 8)
        t[r][x] = src[(size_t)(k0 + r) * N + n0 + x];
    __syncthreads();
    #pragma unroll
    for (int r = threadIdx.y; r < 32; r += 8) {
        int n = n0 + r;
        int nd = inter ? ((n < (N >> 1)) ? 2 * n : 2 * (n - (N >> 1)) + 1) : n;
        dst[(size_t)nd * K + k0 + x] = __float2half_rn(t[x][r]);
    }
}

// Readout GEMM: C[M,N] = A[M,K] @ B[N,K]^T, fp32 accum. BM=128, BN=256,
// BK=64, 3-stage cp.async, single-sync, 256 thr, warp tile 64x64.
__global__ void __launch_bounds__(256, 1)
k_gemm_ro(const __half* __restrict__ A, const __half* __restrict__ B,
          float* __restrict__ C, int M, int N, int K) {
    constexpr int BNv = 256;
    constexpr int STG = A_BYTES + STAGE_B(BNv);

    extern __shared__ __half smem[];
    uint32_t sbase = (uint32_t)__cvta_generic_to_shared(smem);

    int tid  = threadIdx.x;
    int lane = tid & 31, warp = tid >> 5;
    int wm = warp & 1;
    int wn = warp >> 1;
    int bRow = blockIdx.y * BM, bCol = blockIdx.x * BNv;

    const __half* Ab = A + (size_t)bRow * K;
    const __half* Bb = B + (size_t)bCol * K;

    float acc[4][8][4];
    #pragma unroll
    for (int mi = 0; mi < 4; mi++)
        #pragma unroll
        for (int ni = 0; ni < 8; ni++)
            #pragma unroll
            for (int r = 0; r < 4; r++) acc[mi][ni][r] = 0.0f;

    auto load_stage = [&](int st, int kt) {
        uint32_t a0 = sbase + st * STG;
        #pragma unroll
        for (int i = 0; i < 4; i++) {
            int f = tid + i * 256;
            int r = f >> 3, c = f & 7;
            cp16(a0 + (r * PITCH + c * 8) * 2, Ab + (size_t)r * K + kt + c * 8);
        }
        uint32_t b0 = a0 + A_BYTES;
        #pragma unroll
        for (int i = 0; i < 8; i++) {
            int f = tid + i * 256;
            int r = f >> 3, c = f & 7;
            cp16(b0 + (r * PITCH + c * 8) * 2, Bb + (size_t)r * K + kt + c * 8);
        }
    };

    int nt = K / BK;

    #pragma unroll
    for (int s = 0; s < NST - 1; s++) {
        load_stage(s, s * BK);
        asm volatile("cp.async.commit_group;" ::: "memory");
    }

    int aRow = wm * 64 + (lane & 15);
    int aCS  = (lane >> 4) * 8;
    int bMat = lane >> 3;
    int bRowOff = (bMat >> 1) * 8 + (lane & 7);
    int bCS  = (bMat & 1) * 8;

    for (int t = 0; t < nt; t++) {
        if (t < nt - 1)
            asm volatile("cp.async.wait_group 1;" ::: "memory");
        else
            asm volatile("cp.async.wait_group 0;" ::: "memory");
        __syncthreads();

        if (t + NST - 1 < nt) {
            load_stage((t + NST - 1) % NST, (t + NST - 1) * BK);
            asm volatile("cp.async.commit_group;" ::: "memory");
        }

        uint32_t As = sbase + (t % NST) * STG;
        uint32_t Bs = As + A_BYTES;

        #pragma unroll
        for (int kk = 0; kk < 4; kk++) {
            int ks = kk * 16;
            unsigned a[4][4], b[4][4];
            #pragma unroll
            for (int mi = 0; mi < 4; mi++)
                ldsm_x4(a[mi], As + ((aRow + mi * 16) * PITCH + ks + aCS) * 2);
            #pragma unroll
            for (int nb = 0; nb < 4; nb++)
                ldsm_x4(b[nb], Bs + ((wn * 64 + nb * 16 + bRowOff) * PITCH
                                     + ks + bCS) * 2);
            #pragma unroll
            for (int mi = 0; mi < 4; mi++)
                #pragma unroll
                for (int ni = 0; ni < 8; ni++)
                    mma_f16(acc[mi][ni], a[mi], &b[ni >> 1][(ni & 1) * 2]);
        }
    }

    int g = lane >> 2, tg = lane & 3;
    #pragma unroll
    for (int mi = 0; mi < 4; mi++) {
        int r0 = bRow + wm * 64 + mi * 16 + g;
        #pragma unroll
        for (int ni = 0; ni < 8; ni++) {
            int c0 = bCol + wn * 64 + ni * 8 + 2 * tg;
            float2 lo = {acc[mi][ni][0], acc[mi][ni][1]};
            float2 hi = {acc[mi][ni][2], acc[mi][ni][3]};
            *(float2*)(C + (size_t)r0 * N + c0)       = lo;
            *(float2*)(C + (size_t)(r0 + 8) * N + c0) = hi;
        }
    }
}

// Inner GEMM + fused minGRU gate: BM=128, BN=256, 512 threads = 16 warps
// in 2(M)x8(N), warp tile 64x32, 3-stage cp.async, 1 CTA/SM.
// 128 CTAs -> one CTA per SM (no placement doubling imbalance); 16 warps
// = 4/SMSP hide HMMA/LDSM latency within the single CTA.
__global__ void __launch_bounds__(512, 1)
k_gemm_in(const __half* __restrict__ A, const __half* __restrict__ B,
          int K) {
    constexpr int BNv = 256;
    constexpr int STG = A_BYTES + STAGE_B(BNv);

    extern __shared__ __half smem[];
    uint32_t sbase = (uint32_t)__cvta_generic_to_shared(smem);

    int tid  = threadIdx.x;
    int lane = tid & 31, warp = tid >> 5;
    int wm = warp & 1;                 // 2 warps along M (64 each)
    int wn = warp >> 1;                // 8 warps along N (32 each)
    int bRow = blockIdx.y * BM, bCol = blockIdx.x * BNv;

    const __half* Ab = A + (size_t)bRow * K;
    const __half* Bb = B + (size_t)bCol * K;

    float acc[4][4][4];
    #pragma unroll
    for (int mi = 0; mi < 4; mi++)
        #pragma unroll
        for (int ni = 0; ni < 4; ni++)
            #pragma unroll
            for (int r = 0; r < 4; r++) acc[mi][ni][r] = 0.0f;

    auto load_stage = [&](int st, int kt) {
        uint32_t a0 = sbase + st * STG;
        #pragma unroll
        for (int i = 0; i < 2; i++) {
            int f = tid + i * 512;
            int r = f >> 3, c = f & 7;
            cp16(a0 + (r * PITCH + c * 8) * 2, Ab + (size_t)r * K + kt + c * 8);
        }
        uint32_t b0 = a0 + A_BYTES;
        #pragma unroll
        for (int i = 0; i < 4; i++) {
            int f = tid + i * 512;
            int r = f >> 3, c = f & 7;
            cp16(b0 + (r * PITCH + c * 8) * 2, Bb + (size_t)r * K + kt + c * 8);
        }
    };

    int nt = K / BK;     // 8

    #pragma unroll
    for (int s = 0; s < NST - 1; s++) {
        load_stage(s, s * BK);
        asm volatile("cp.async.commit_group;" ::: "memory");
    }

    int aRow = wm * 64 + (lane & 15);
    int aCS  = (lane >> 4) * 8;
    int bMat = lane >> 3;
    int bRowOff = (bMat >> 1) * 8 + (lane & 7);
    int bCS  = (bMat & 1) * 8;

    for (int t = 0; t < nt; t++) {
        if (t < nt - 1)
            asm volatile("cp.async.wait_group 1;" ::: "memory");
        else
            asm volatile("cp.async.wait_group 0;" ::: "memory");
        __syncthreads();

        if (t + NST - 1 < nt) {
            load_stage((t + NST - 1) % NST, (t + NST - 1) * BK);
            asm volatile("cp.async.commit_group;" ::: "memory");
        }

        uint32_t As = sbase + (t % NST) * STG;
        uint32_t Bs = As + A_BYTES;

        #pragma unroll
        for (int kk = 0; kk < 4; kk++) {
            int ks = kk * 16;
            unsigned a[4][4], b[2][4];
            #pragma unroll
            for (int mi = 0; mi < 4; mi++)
                ldsm_x4(a[mi], As + ((aRow + mi * 16) * PITCH + ks + aCS) * 2);
            #pragma unroll
            for (int nb = 0; nb < 2; nb++)
                ldsm_x4(b[nb], Bs + ((wn * 32 + nb * 16 + bRowOff) * PITCH
                                     + ks + bCS) * 2);
            #pragma unroll
            for (int mi = 0; mi < 4; mi++)
                #pragma unroll
                for (int ni = 0; ni < 4; ni++)
                    mma_f16(acc[mi][ni], a[mi], &b[ni >> 1][(ni & 1) * 2]);
        }
    }

    int g = lane >> 2, tg = lane & 3;
    // cols (c0, c0+1) = (hidden_d, gate_d), d = c0/2 (interleaved weights)
    #pragma unroll
    for (int mi = 0; mi < 4; mi++) {
        int r0 = bRow + wm * 64 + mi * 16 + g;
        #pragma unroll
        for (int ni = 0; ni < 4; ni++) {
            int d0 = (bCol >> 1) + wn * 16 + ni * 4 + tg;
            #pragma unroll
            for (int h = 0; h < 2; h++) {
                int r = r0 + 8 * h;
                float hd = acc[mi][ni][2 * h];
                float q  = acc[mi][ni][2 * h + 1];
                float eq = __expf(q);
                float cc = 1.0f / (1.0f + eq);          // sigmoid(-q)
                float z  = eq * cc;                     // sigmoid(q)
                float gg = hd >= 0.0f ? hd + 0.5f
                                      : 1.0f / (1.0f + __expf(-hd));
                g_c[(size_t)r * DIM + d0] = cc;
                g_v[(size_t)r * DIM + d0] = z * gg;
            }
        }
    }
}

// Fused chunked scan: publish (P,S), spin on predecessors, back-scan,
// apply + residual. 256 blocks, all resident.
__global__ void __launch_bounds__(128) k_scan() {
    extern __shared__ float ssm[];
    float* sc = ssm;
    float* sv = ssm + CHUNK * 128;

    int ch  = blockIdx.x;                      // 0..63
    int dg  = blockIdx.y;                      // 0..3
    int tid = threadIdx.x;
    int d   = dg * 128 + tid;

    float P = 1.0f, S = 0.0f;
    #pragma unroll 4
    for (int j = 0; j < CHUNK; j++) {
        int idx = (ch * CHUNK + j) * DIM + d;
        float c = g_c[idx], v = g_v[idx];
        sc[j * 128 + tid] = c;
        sv[j * 128 + tid] = v;
        P *= c;
        S = fmaf(c, S, v);
    }
    g_P[ch * DIM + d] = P;
    g_S[ch * DIM + d] = S;
    __threadfence();
    __syncthreads();
    if (tid == 0)
        *((volatile int*)&g_flag[dg * NCH + ch]) = 1;

    if (tid < ch) {
        volatile int* f = &g_flag[dg * NCH + tid];
        while (*f == 0) __nanosleep(40);
    }
    __syncthreads();
    __threadfence();

    float h = 0.0f;
    for (int j = 0; j < ch; j++)
        h = fmaf(g_P[j * DIM + d], h, g_S[j * DIM + d]);

    #pragma unroll 4
    for (int j = 0; j < CHUNK; j++) {
        h = fmaf(sc[j * 128 + tid], h, sv[j * 128 + tid]);
        int idx = (ch * CHUNK + j) * DIM + d;
        g_x[idx] += h;
    }
}

// ---------------- host -----------------------------------------------------
extern "C" void kernel_launch(void* const* d_in, const int* in_sizes, int n_in,
                              void* d_out, int out_size) {
    const int*   ids    = (const int*)  d_in[0];
    const float* emb    = (const float*)d_in[1];
    const float* w_hg   = (const float*)d_in[2];
    const float* nscale = (const float*)d_in[3];
    const float* fscale = (const float*)d_in[4];
    const float* rw     = (const float*)d_in[5];
    float*       out    = (float*)d_out;

    static bool attr_set = false;
    if (!attr_set) {
        cudaFuncSetAttribute(k_gemm_in,
                             cudaFuncAttributeMaxDynamicSharedMemorySize, GSMEM(256));
        cudaFuncSetAttribute(k_gemm_ro,
                             cudaFuncAttributeMaxDynamicSharedMemorySize, GSMEM(256));
        cudaFuncSetAttribute(k_scan,
                             cudaFuncAttributeMaxDynamicSharedMemorySize, SCAN_SMEM);
        attr_set = true;
    }

    __half *pwt = nullptr, *prwt = nullptr, *pxn = nullptr;
    cudaGetSymbolAddress((void**)&pxn,  g_xn);
    cudaGetSymbolAddress((void**)&pwt,  g_wt);
    cudaGetSymbolAddress((void**)&prwt, g_rwt);

    // prepass: all 4 block weights in one launch (interleaved), readout plain
    k_transpose<<<dim3(HD2 / 32, DIM / 32, NBLK), dim3(32, 8)>>>(
        w_hg, pwt, DIM, HD2, 1, (size_t)DIM * HD2, (size_t)HD2 * DIM);
    k_transpose<<<dim3(VOCAB / 32, DIM / 32, 1), dim3(32, 8)>>>(
        rw, prwt, DIM, VOCAB, 0, 0, 0);

    for (int i = 0; i < NBLK; i++) {
        if (i == 0)
            k_rmsnorm<true><<<SEQ / 4, 128>>>(nscale, ids, emb);
        else
            k_rmsnorm<false><<<SEQ / 4, 128>>>(nscale + i * DIM, ids, emb);
        k_gemm_in<<<dim3(HD2 / 256, SEQ / BM), 512, GSMEM(256)>>>(
            pxn, pwt + (size_t)i * HD2 * DIM, DIM);
        k_scan<<<dim3(NCH, 4), 128, SCAN_SMEM>>>();
    }

    k_rmsnorm<false><<<SEQ / 4, 128>>>(fscale, ids, emb);
    k_gemm_ro<<<dim3(VOCAB / 256, SEQ / BM), 256, GSMEM(256)>>>(
        pxn, prwt, out, SEQ, VOCAB, DIM);
}

// round 11
// speedup vs baseline: 2.4443x; 1.0993x over previous
#include <cuda_runtime.h>
#include <cuda_fp16.h>
#include <cstdint>

#define SEQ    4096
#define DIM    512
#define VOCAB  32000
#define NBLK   4
#define HD2    (2*DIM)
#define CHUNK  64
#define NCH    (SEQ/CHUNK)

// ---- shared GEMM tiling constants ----
#define BM 128
#define BK 64
#define NST 3
#define PITCH 72                        // halves per smem row (64 + 8 pad)
#define A_BYTES (BM*PITCH*2)            // 18432
#define STAGE_B(BNv) ((BNv)*PITCH*2)
#define GSMEM(BNv)   (NST*(A_BYTES + STAGE_B(BNv)))   // BN=256 -> 165888
#define CVPITCH 132                     // floats per smem c/v row (128+4)

// ---------------- scratch (device globals; no allocation allowed) ----------
__device__ float  g_x [SEQ*DIM];
__device__ __half g_xn[SEQ*DIM];
__device__ float  g_P [NCH*DIM];
__device__ float  g_S [NCH*DIM];
__device__ int    g_flag[4*NCH];
__device__ __half g_wt [NBLK*HD2*DIM];          // transposed+interleaved fp16
__device__ __half g_rwt[(size_t)VOCAB*DIM];     // transposed fp16 readout

// ---------------- helpers --------------------------------------------------
__device__ __forceinline__ void cp16(uint32_t saddr, const void* g) {
    asm volatile("cp.async.cg.shared.global [%0], [%1], 16;\n"
                 :: "r"(saddr), "l"(g));
}

__device__ __forceinline__ void ldsm_x4(unsigned* r, uint32_t addr) {
    asm volatile("ldmatrix.sync.aligned.m8n8.x4.shared.b16 {%0,%1,%2,%3}, [%4];"
                 : "=r"(r[0]), "=r"(r[1]), "=r"(r[2]), "=r"(r[3]) : "r"(addr));
}

__device__ __forceinline__ void mma_f16(float* d, const unsigned* a,
                                        const unsigned* b) {
    asm volatile(
        "mma.sync.aligned.m16n8k16.row.col.f32.f16.f16.f32 "
        "{%0,%1,%2,%3}, {%4,%5,%6,%7}, {%8,%9}, {%0,%1,%2,%3};"
        : "+f"(d[0]), "+f"(d[1]), "+f"(d[2]), "+f"(d[3])
        : "r"(a[0]), "r"(a[1]), "r"(a[2]), "r"(a[3]),
          "r"(b[0]), "r"(b[1]));
}

// ---------------- kernels --------------------------------------------------

// Warp-per-row RMSNorm -> fp16. GATHER: fused embedding gather (also fills
// g_x). Also re-zeros scan flags (stream-ordered before the next k_block).
template <bool GATHER>
__global__ void __launch_bounds__(128) k_rmsnorm(
        const float* __restrict__ scale,
        const int* __restrict__ ids, const float* __restrict__ emb) {
    if (blockIdx.x < 2) g_flag[blockIdx.x * 128 + threadIdx.x] = 0;

    int warp = threadIdx.x >> 5, lane = threadIdx.x & 31;
    int row  = blockIdx.x * 4 + warp;

    const float4* src = GATHER
        ? (const float4*)(emb + (size_t)ids[row] * DIM)
        : (const float4*)(g_x + (size_t)row * DIM);

    float4 v[4];
    float s = 0.0f;
    #pragma unroll
    for (int j = 0; j < 4; j++) {
        v[j] = src[lane + 32 * j];
        s += v[j].x*v[j].x + v[j].y*v[j].y + v[j].z*v[j].z + v[j].w*v[j].w;
    }
    #pragma unroll
    for (int o = 16; o; o >>= 1) s += __shfl_xor_sync(0xFFFFFFFFu, s, o);
    float r = rsqrtf(s * (1.0f / DIM) + 1e-6f);

    float4* dx  = (float4*)(g_x  + (size_t)row * DIM);
    uint2*  dxn = (uint2*)(g_xn + (size_t)row * DIM);
    #pragma unroll
    for (int j = 0; j < 4; j++) {
        if (GATHER) dx[lane + 32 * j] = v[j];
        float4 sc = ((const float4*)scale)[lane + 32 * j];
        __half2 h0 = __floats2half2_rn(v[j].x * r * sc.x, v[j].y * r * sc.y);
        __half2 h1 = __floats2half2_rn(v[j].z * r * sc.z, v[j].w * r * sc.w);
        uint2 o = {*(unsigned*)&h0, *(unsigned*)&h1};
        dxn[lane + 32 * j] = o;
    }
}

// Transpose + fp16: src [K,N] fp32 -> dst [N',K] fp16.
// inter!=0 remaps output row: n<N/2 -> 2n (hidden), else 2(n-N/2)+1 (gate).
__global__ void k_transpose(const float* __restrict__ src,
                            __half* __restrict__ dst, int K, int N, int inter,
                            size_t sstride, size_t dstride) {
    src += blockIdx.z * sstride;
    dst += blockIdx.z * dstride;
    __shared__ float t[32][33];
    int n0 = blockIdx.x * 32, k0 = blockIdx.y * 32;
    int x = threadIdx.x;
    #pragma unroll
    for (int r = threadIdx.y; r < 32; r += 8)
        t[r][x] = src[(size_t)(k0 + r) * N + n0 + x];
    __syncthreads();
    #pragma unroll
    for (int r = threadIdx.y; r < 32; r += 8) {
        int n = n0 + r;
        int nd = inter ? ((n < (N >> 1)) ? 2 * n : 2 * (n - (N >> 1)) + 1) : n;
        dst[(size_t)nd * K + k0 + x] = __float2half_rn(t[x][r]);
    }
}

// Readout GEMM: C[M,N] = A[M,K] @ B[N,K]^T, fp32 accum. BM=128, BN=256,
// BK=64, 3-stage cp.async, single-sync, 256 thr, warp tile 64x64.
__global__ void __launch_bounds__(256, 1)
k_gemm_ro(const __half* __restrict__ A, const __half* __restrict__ B,
          float* __restrict__ C, int M, int N, int K) {
    constexpr int BNv = 256;
    constexpr int STG = A_BYTES + STAGE_B(BNv);

    extern __shared__ __half smem[];
    uint32_t sbase = (uint32_t)__cvta_generic_to_shared(smem);

    int tid  = threadIdx.x;
    int lane = tid & 31, warp = tid >> 5;
    int wm = warp & 1;
    int wn = warp >> 1;
    int bRow = blockIdx.y * BM, bCol = blockIdx.x * BNv;

    const __half* Ab = A + (size_t)bRow * K;
    const __half* Bb = B + (size_t)bCol * K;

    float acc[4][8][4];
    #pragma unroll
    for (int mi = 0; mi < 4; mi++)
        #pragma unroll
        for (int ni = 0; ni < 8; ni++)
            #pragma unroll
            for (int r = 0; r < 4; r++) acc[mi][ni][r] = 0.0f;

    auto load_stage = [&](int st, int kt) {
        uint32_t a0 = sbase + st * STG;
        #pragma unroll
        for (int i = 0; i < 4; i++) {
            int f = tid + i * 256;
            int r = f >> 3, c = f & 7;
            cp16(a0 + (r * PITCH + c * 8) * 2, Ab + (size_t)r * K + kt + c * 8);
        }
        uint32_t b0 = a0 + A_BYTES;
        #pragma unroll
        for (int i = 0; i < 8; i++) {
            int f = tid + i * 256;
            int r = f >> 3, c = f & 7;
            cp16(b0 + (r * PITCH + c * 8) * 2, Bb + (size_t)r * K + kt + c * 8);
        }
    };

    int nt = K / BK;

    #pragma unroll
    for (int s = 0; s < NST - 1; s++) {
        load_stage(s, s * BK);
        asm volatile("cp.async.commit_group;" ::: "memory");
    }

    int aRow = wm * 64 + (lane & 15);
    int aCS  = (lane >> 4) * 8;
    int bMat = lane >> 3;
    int bRowOff = (bMat >> 1) * 8 + (lane & 7);
    int bCS  = (bMat & 1) * 8;

    for (int t = 0; t < nt; t++) {
        if (t < nt - 1)
            asm volatile("cp.async.wait_group 1;" ::: "memory");
        else
            asm volatile("cp.async.wait_group 0;" ::: "memory");
        __syncthreads();

        if (t + NST - 1 < nt) {
            load_stage((t + NST - 1) % NST, (t + NST - 1) * BK);
            asm volatile("cp.async.commit_group;" ::: "memory");
        }

        uint32_t As = sbase + (t % NST) * STG;
        uint32_t Bs = As + A_BYTES;

        #pragma unroll
        for (int kk = 0; kk < 4; kk++) {
            int ks = kk * 16;
            unsigned a[4][4], b[4][4];
            #pragma unroll
            for (int mi = 0; mi < 4; mi++)
                ldsm_x4(a[mi], As + ((aRow + mi * 16) * PITCH + ks + aCS) * 2);
            #pragma unroll
            for (int nb = 0; nb < 4; nb++)
                ldsm_x4(b[nb], Bs + ((wn * 64 + nb * 16 + bRowOff) * PITCH
                                     + ks + bCS) * 2);
            #pragma unroll
            for (int mi = 0; mi < 4; mi++)
                #pragma unroll
                for (int ni = 0; ni < 8; ni++)
                    mma_f16(acc[mi][ni], a[mi], &b[ni >> 1][(ni & 1) * 2]);
        }
    }

    int g = lane >> 2, tg = lane & 3;
    #pragma unroll
    for (int mi = 0; mi < 4; mi++) {
        int r0 = bRow + wm * 64 + mi * 16 + g;
        #pragma unroll
        for (int ni = 0; ni < 8; ni++) {
            int c0 = bCol + wn * 64 + ni * 8 + 2 * tg;
            float2 lo = {acc[mi][ni][0], acc[mi][ni][1]};
            float2 hi = {acc[mi][ni][2], acc[mi][ni][3]};
            *(float2*)(C + (size_t)r0 * N + c0)       = lo;
            *(float2*)(C + (size_t)(r0 + 8) * N + c0) = hi;
        }
    }
}

// Fused minGRU block: GEMM (BM=128 x BN=256 interleaved, BK=64, 3-stage
// cp.async, 512 thr = 2(M)x8(N) warps, warp tile 64x32) + gate epilogue
// into SMEM (reusing dead pipeline stages) + chunked scan (2 chunks x 128
// channels per CTA) with cross-CTA flag chaining + residual into g_x.
// grid (4, 32) = 128 CTAs, 1/SM, all resident -> spin is deadlock-free.
__global__ void __launch_bounds__(512, 1)
k_block(const __half* __restrict__ A, const __half* __restrict__ B) {
    constexpr int K = DIM;
    constexpr int BNv = 256;
    constexpr int STG = A_BYTES + STAGE_B(BNv);

    extern __shared__ __half smem[];
    uint32_t sbase = (uint32_t)__cvta_generic_to_shared(smem);
    float* sc = (float*)smem;                  // c tile [128][CVPITCH]
    float* sv = sc + 128 * CVPITCH;            // v tile [128][CVPITCH]

    int tid  = threadIdx.x;
    int lane = tid & 31, warp = tid >> 5;
    int wm = warp & 1;                 // 2 warps along M (64 each)
    int wn = warp >> 1;                // 8 warps along N (32 each)
    int bx = blockIdx.x;               // channel group (0..3)
    int by = blockIdx.y;               // time tile (0..31)
    int bRow = by * BM, bCol = bx * BNv;

    const __half* Ab = A + (size_t)bRow * K;
    const __half* Bb = B + (size_t)bCol * K;

    float acc[4][4][4];
    #pragma unroll
    for (int mi = 0; mi < 4; mi++)
        #pragma unroll
        for (int ni = 0; ni < 4; ni++)
            #pragma unroll
            for (int r = 0; r < 4; r++) acc[mi][ni][r] = 0.0f;

    auto load_stage = [&](int st, int kt) {
        uint32_t a0 = sbase + st * STG;
        #pragma unroll
        for (int i = 0; i < 2; i++) {
            int f = tid + i * 512;
            int r = f >> 3, c = f & 7;
            cp16(a0 + (r * PITCH + c * 8) * 2, Ab + (size_t)r * K + kt + c * 8);
        }
        uint32_t b0 = a0 + A_BYTES;
        #pragma unroll
        for (int i = 0; i < 4; i++) {
            int f = tid + i * 512;
            int r = f >> 3, c = f & 7;
            cp16(b0 + (r * PITCH + c * 8) * 2, Bb + (size_t)r * K + kt + c * 8);
        }
    };

    int nt = K / BK;     // 8

    #pragma unroll
    for (int s = 0; s < NST - 1; s++) {
        load_stage(s, s * BK);
        asm volatile("cp.async.commit_group;" ::: "memory");
    }

    int aRow = wm * 64 + (lane & 15);
    int aCS  = (lane >> 4) * 8;
    int bMat = lane >> 3;
    int bRowOff = (bMat >> 1) * 8 + (lane & 7);
    int bCS  = (bMat & 1) * 8;

    for (int t = 0; t < nt; t++) {
        if (t < nt - 1)
            asm volatile("cp.async.wait_group 1;" ::: "memory");
        else
            asm volatile("cp.async.wait_group 0;" ::: "memory");
        __syncthreads();

        if (t + NST - 1 < nt) {
            load_stage((t + NST - 1) % NST, (t + NST - 1) * BK);
            asm volatile("cp.async.commit_group;" ::: "memory");
        }

        uint32_t As = sbase + (t % NST) * STG;
        uint32_t Bs = As + A_BYTES;

        #pragma unroll
        for (int kk = 0; kk < 4; kk++) {
            int ks = kk * 16;
            unsigned a[4][4], b[2][4];
            #pragma unroll
            for (int mi = 0; mi < 4; mi++)
                ldsm_x4(a[mi], As + ((aRow + mi * 16) * PITCH + ks + aCS) * 2);
            #pragma unroll
            for (int nb = 0; nb < 2; nb++)
                ldsm_x4(b[nb], Bs + ((wn * 32 + nb * 16 + bRowOff) * PITCH
                                     + ks + bCS) * 2);
            #pragma unroll
            for (int mi = 0; mi < 4; mi++)
                #pragma unroll
                for (int ni = 0; ni < 4; ni++)
                    mma_f16(acc[mi][ni], a[mi], &b[ni >> 1][(ni & 1) * 2]);
        }
    }
    __syncthreads();   // all stage smem reads done before c/v overwrite

    // ---- gate epilogue into smem: (hidden,gate) col pairs -> c,v ----
    int g = lane >> 2, tg = lane & 3;
    #pragma unroll
    for (int mi = 0; mi < 4; mi++) {
        int r0 = wm * 64 + mi * 16 + g;          // local time row
        #pragma unroll
        for (int ni = 0; ni < 4; ni++) {
            int d0 = wn * 16 + ni * 4 + tg;      // local channel
            #pragma unroll
            for (int h = 0; h < 2; h++) {
                int r = r0 + 8 * h;
                float hd = acc[mi][ni][2 * h];
                float q  = acc[mi][ni][2 * h + 1];
                float eq = __expf(q);
                float cc = 1.0f / (1.0f + eq);          // sigmoid(-q)
                float z  = eq * cc;                     // sigmoid(q)
                float gg = hd >= 0.0f ? hd + 0.5f
                                      : 1.0f / (1.0f + __expf(-hd));
                sc[r * CVPITCH + d0] = cc;
                sv[r * CVPITCH + d0] = z * gg;
            }
        }
    }
    __syncthreads();

    // ---- scan: this CTA owns chunks (2*by, 2*by+1) x channels bx*128.. ----
    int ch = tid >> 7;                 // 0..1 (threads 0..255 active)
    int c  = tid & 127;
    int dglob = bx * 128 + c;

    if (tid < 256) {
        float P = 1.0f, S = 0.0f;
        #pragma unroll 8
        for (int j = 0; j < CHUNK; j++) {
            float cc = sc[(ch * CHUNK + j) * CVPITCH + c];
            float vv = sv[(ch * CHUNK + j) * CVPITCH + c];
            P *= cc;
            S = fmaf(cc, S, vv);
        }
        int CH = 2 * by + ch;
        g_P[CH * DIM + dglob] = P;
        g_S[CH * DIM + dglob] = S;
    }
    __threadfence();
    __syncthreads();
    if (tid == 0) {
        *((volatile int*)&g_flag[bx * NCH + 2 * by])     = 1;
        *((volatile int*)&g_flag[bx * NCH + 2 * by + 1]) = 1;
    }

    // spin on predecessor chunks (< 2*by) of this channel group
    if (tid < 2 * by) {
        volatile int* f = &g_flag[bx * NCH + tid];
        while (*f == 0) __nanosleep(40);
    }
    __syncthreads();
    __threadfence();

    if (tid < 256) {
        int CH = 2 * by + ch;
        float h = 0.0f;
        for (int j = 0; j < CH; j++)
            h = fmaf(g_P[j * DIM + dglob], h, g_S[j * DIM + dglob]);

        #pragma unroll 8
        for (int j = 0; j < CHUNK; j++) {
            float cc = sc[(ch * CHUNK + j) * CVPITCH + c];
            float vv = sv[(ch * CHUNK + j) * CVPITCH + c];
            h = fmaf(cc, h, vv);
            g_x[(size_t)(CH * CHUNK + j) * DIM + dglob] += h;
        }
    }
}

// ---------------- host -----------------------------------------------------
extern "C" void kernel_launch(void* const* d_in, const int* in_sizes, int n_in,
                              void* d_out, int out_size) {
    const int*   ids    = (const int*)  d_in[0];
    const float* emb    = (const float*)d_in[1];
    const float* w_hg   = (const float*)d_in[2];
    const float* nscale = (const float*)d_in[3];
    const float* fscale = (const float*)d_in[4];
    const float* rw     = (const float*)d_in[5];
    float*       out    = (float*)d_out;

    static bool attr_set = false;
    if (!attr_set) {
        cudaFuncSetAttribute(k_block,
                             cudaFuncAttributeMaxDynamicSharedMemorySize, GSMEM(256));
        cudaFuncSetAttribute(k_gemm_ro,
                             cudaFuncAttributeMaxDynamicSharedMemorySize, GSMEM(256));
        attr_set = true;
    }

    __half *pwt = nullptr, *prwt = nullptr, *pxn = nullptr;
    cudaGetSymbolAddress((void**)&pxn,  g_xn);
    cudaGetSymbolAddress((void**)&pwt,  g_wt);
    cudaGetSymbolAddress((void**)&prwt, g_rwt);

    // prepass: all 4 block weights in one launch (interleaved), readout plain
    k_transpose<<<dim3(HD2 / 32, DIM / 32, NBLK), dim3(32, 8)>>>(
        w_hg, pwt, DIM, HD2, 1, (size_t)DIM * HD2, (size_t)HD2 * DIM);
    k_transpose<<<dim3(VOCAB / 32, DIM / 32, 1), dim3(32, 8)>>>(
        rw, prwt, DIM, VOCAB, 0, 0, 0);

    for (int i = 0; i < NBLK; i++) {
        if (i == 0)
            k_rmsnorm<true><<<SEQ / 4, 128>>>(nscale, ids, emb);
        else
            k_rmsnorm<false><<<SEQ / 4, 128>>>(nscale + i * DIM, ids, emb);
        k_block<<<dim3(HD2 / 256, SEQ / BM), 512, GSMEM(256)>>>(
            pxn, pwt + (size_t)i * HD2 * DIM);
    }

    k_rmsnorm<false><<<SEQ / 4, 128>>>(fscale, ids, emb);
    k_gemm_ro<<<dim3(VOCAB / 256, SEQ / BM), 256, GSMEM(256)>>>(
        pxn, prwt, out, SEQ, VOCAB, DIM);
}